// round 1
// baseline (speedup 1.0000x reference)
#include <cuda_runtime.h>
#include <math.h>

// Problem constants
#define BATCH   40
#define NSEQ    257
#define DMODEL  1024
#define FFDIM   4096
#define NHEAD   16
#define HDIM    64
#define TOK     (BATCH * NSEQ)      // 10280
#define QK_SCALE 0.125f             // 64^-0.5

// ---------------- scratch (allocation-free: __device__ globals) ----------------
__device__ float g_xln   [TOK * DMODEL];
__device__ float g_q     [TOK * DMODEL];
__device__ float g_k     [TOK * DMODEL];
__device__ float g_v     [TOK * DMODEL];
__device__ float g_attn  [TOK * DMODEL];
__device__ float g_hidden[TOK * DMODEL];
__device__ float g_h2    [TOK * DMODEL];
__device__ float g_ff    [TOK * FFDIM];

// ---------------- warp/block reduce helpers ----------------
__device__ __forceinline__ float warpSum(float v) {
    #pragma unroll
    for (int o = 16; o > 0; o >>= 1) v += __shfl_xor_sync(0xffffffffu, v, o);
    return v;
}
__device__ __forceinline__ float warpMax(float v) {
    #pragma unroll
    for (int o = 16; o > 0; o >>= 1) v = fmaxf(v, __shfl_xor_sync(0xffffffffu, v, o));
    return v;
}

// ---------------- LayerNorm: one block per row, 256 threads, float4 ----------------
__global__ void ln_kernel(const float* __restrict__ x,
                          const float* __restrict__ w,
                          const float* __restrict__ b,
                          float* __restrict__ y)
{
    int row = blockIdx.x;
    int tid = threadIdx.x;                 // 256 threads, 4 floats each
    const float* xr = x + (size_t)row * DMODEL;
    float4 v = *(const float4*)&xr[tid * 4];

    float s  = v.x + v.y + v.z + v.w;
    float s2 = v.x * v.x + v.y * v.y + v.z * v.z + v.w * v.w;

    __shared__ float redS[8], redS2[8];
    int lane = tid & 31, wid = tid >> 5;
    s  = warpSum(s);
    s2 = warpSum(s2);
    if (lane == 0) { redS[wid] = s; redS2[wid] = s2; }
    __syncthreads();
    float ts = 0.f, ts2 = 0.f;
    #pragma unroll
    for (int i = 0; i < 8; i++) { ts += redS[i]; ts2 += redS2[i]; }
    float mean = ts * (1.0f / DMODEL);
    float var  = ts2 * (1.0f / DMODEL) - mean * mean;
    float r    = rsqrtf(var + 1e-5f);

    float4 wv = *(const float4*)&w[tid * 4];
    float4 bv = *(const float4*)&b[tid * 4];
    float4 o;
    o.x = (v.x - mean) * r * wv.x + bv.x;
    o.y = (v.y - mean) * r * wv.y + bv.y;
    o.z = (v.z - mean) * r * wv.z + bv.z;
    o.w = (v.w - mean) * r * wv.w + bv.w;
    *(float4*)&(y + (size_t)row * DMODEL)[tid * 4] = o;
}

// ---------------- Tiled NT GEMM: C[M,N] = epilogue(A[M,K] @ B[N,K]^T + bias) ----------------
// MODE 0: (acc + bias) * alpha
// MODE 1: quick_gelu(acc + bias)
// MODE 2: acc + bias + res[row,col]
#define BM 64
#define BN 64
#define BKK 16

template<int MODE>
__global__ __launch_bounds__(256)
void gemm_nt(const float* __restrict__ A, const float* __restrict__ B,
             const float* __restrict__ bias, const float* __restrict__ res,
             float* __restrict__ C, int M, int N, int K, float alpha)
{
    __shared__ float As[BKK][BM + 4];
    __shared__ float Bs[BKK][BN + 4];

    int tid = threadIdx.x;                 // 256
    int bm = blockIdx.y * BM;
    int bn = blockIdx.x * BN;

    int lrow = tid >> 2;                   // 0..63
    int lcol = (tid & 3) * 4;              // 0,4,8,12
    int ty = tid >> 4;                     // 0..15
    int tx = tid & 15;                     // 0..15

    float acc[4][4] = {};

    for (int k0 = 0; k0 < K; k0 += BKK) {
        // load A tile (row-guarded), B tile (N is always a multiple of 64)
        float4 av = make_float4(0.f, 0.f, 0.f, 0.f);
        int ar = bm + lrow;
        if (ar < M) av = *(const float4*)&A[(size_t)ar * K + k0 + lcol];
        As[lcol + 0][lrow] = av.x;
        As[lcol + 1][lrow] = av.y;
        As[lcol + 2][lrow] = av.z;
        As[lcol + 3][lrow] = av.w;

        float4 bv = *(const float4*)&B[(size_t)(bn + lrow) * K + k0 + lcol];
        Bs[lcol + 0][lrow] = bv.x;
        Bs[lcol + 1][lrow] = bv.y;
        Bs[lcol + 2][lrow] = bv.z;
        Bs[lcol + 3][lrow] = bv.w;

        __syncthreads();

        #pragma unroll
        for (int kk = 0; kk < BKK; kk++) {
            float4 a4 = *(const float4*)&As[kk][ty * 4];
            float4 b4 = *(const float4*)&Bs[kk][tx * 4];
            float a[4] = {a4.x, a4.y, a4.z, a4.w};
            float b[4] = {b4.x, b4.y, b4.z, b4.w};
            #pragma unroll
            for (int i = 0; i < 4; i++)
                #pragma unroll
                for (int j = 0; j < 4; j++)
                    acc[i][j] = fmaf(a[i], b[j], acc[i][j]);
        }
        __syncthreads();
    }

    #pragma unroll
    for (int i = 0; i < 4; i++) {
        int row = bm + ty * 4 + i;
        if (row >= M) continue;
        #pragma unroll
        for (int j = 0; j < 4; j++) {
            int col = bn + tx * 4 + j;
            float v = acc[i][j] + bias[col];
            if (MODE == 0) {
                v *= alpha;
            } else if (MODE == 1) {
                v = v / (1.0f + expf(-1.702f * v));   // quick gelu
            } else { // MODE == 2
                v += res[(size_t)row * N + col];
            }
            C[(size_t)row * N + col] = v;
        }
    }
}

// ---------------- Attention: one block per (bh, q-row), 128 threads ----------------
__global__ __launch_bounds__(128)
void attn_kernel(const float* __restrict__ Q, const float* __restrict__ K,
                 const float* __restrict__ V, float* __restrict__ O)
{
    int qi = blockIdx.x;                   // 0..256
    int bh = blockIdx.y;                   // 0..639
    int b = bh >> 4, h = bh & 15;
    size_t base = (size_t)b * NSEQ * DMODEL + (size_t)h * HDIM;

    __shared__ float qs[HDIM];
    __shared__ float sc[NSEQ];
    __shared__ float red[4];
    __shared__ float oacc[128];

    int tid = threadIdx.x;                 // 128
    int lane = tid & 31, wid = tid >> 5;

    if (tid < HDIM) qs[tid] = Q[base + (size_t)qi * DMODEL + tid];
    __syncthreads();

    // scores (Q is pre-scaled by QK_SCALE in the projection)
    for (int k = tid; k < NSEQ; k += 128) {
        const float* krow = K + base + (size_t)k * DMODEL;
        float s = 0.f;
        #pragma unroll
        for (int d = 0; d < HDIM; d++) s = fmaf(qs[d], krow[d], s);
        sc[k] = s;
    }
    __syncthreads();

    // max
    float m = -1e30f;
    for (int k = tid; k < NSEQ; k += 128) m = fmaxf(m, sc[k]);
    m = warpMax(m);
    if (lane == 0) red[wid] = m;
    __syncthreads();
    float gm = fmaxf(fmaxf(red[0], red[1]), fmaxf(red[2], red[3]));
    __syncthreads();

    // exp + sum
    float ls = 0.f;
    for (int k = tid; k < NSEQ; k += 128) {
        float e = expf(sc[k] - gm);
        sc[k] = e;
        ls += e;
    }
    ls = warpSum(ls);
    if (lane == 0) red[wid] = ls;
    __syncthreads();
    float inv = 1.0f / (red[0] + red[1] + red[2] + red[3]);
    __syncthreads();

    // out = (attn @ V) * inv ; split k-range across two halves of the block
    int d = tid & 63;
    int half = tid >> 6;
    float acc = 0.f;
    for (int k = half; k < NSEQ; k += 2)
        acc = fmaf(sc[k], V[base + (size_t)k * DMODEL + d], acc);
    oacc[tid] = acc;
    __syncthreads();
    if (tid < HDIM)
        O[base + (size_t)qi * DMODEL + tid] = (oacc[tid] + oacc[tid + 64]) * inv;
}

// ---------------- launch ----------------
extern "C" void kernel_launch(void* const* d_in, const int* in_sizes, int n_in,
                              void* d_out, int out_size)
{
    const float* hs     = (const float*)d_in[0];
    const float* ln1_w  = (const float*)d_in[1];
    const float* ln1_b  = (const float*)d_in[2];
    const float* wq     = (const float*)d_in[3];
    const float* bq     = (const float*)d_in[4];
    const float* wk     = (const float*)d_in[5];
    const float* bk     = (const float*)d_in[6];
    const float* wv     = (const float*)d_in[7];
    const float* bv     = (const float*)d_in[8];
    const float* wo     = (const float*)d_in[9];
    const float* bo     = (const float*)d_in[10];
    const float* ln2_w  = (const float*)d_in[11];
    const float* ln2_b  = (const float*)d_in[12];
    const float* fc1_w  = (const float*)d_in[13];
    const float* fc1_b  = (const float*)d_in[14];
    const float* fc2_w  = (const float*)d_in[15];
    const float* fc2_b  = (const float*)d_in[16];
    float* out          = (float*)d_out;

    static float *xln = nullptr, *q = nullptr, *k = nullptr, *v = nullptr,
                 *attn = nullptr, *hidden = nullptr, *h2 = nullptr, *ff = nullptr;
    if (!xln) {
        cudaGetSymbolAddress((void**)&xln,    g_xln);
        cudaGetSymbolAddress((void**)&q,      g_q);
        cudaGetSymbolAddress((void**)&k,      g_k);
        cudaGetSymbolAddress((void**)&v,      g_v);
        cudaGetSymbolAddress((void**)&attn,   g_attn);
        cudaGetSymbolAddress((void**)&hidden, g_hidden);
        cudaGetSymbolAddress((void**)&h2,     g_h2);
        cudaGetSymbolAddress((void**)&ff,     g_ff);
    }

    const int mtiles = (TOK + BM - 1) / BM;      // 161

    // 1) LN1
    ln_kernel<<<TOK, 256>>>(hs, ln1_w, ln1_b, xln);

    // 2-4) QKV projections (Q pre-scaled)
    gemm_nt<0><<<dim3(DMODEL / BN, mtiles), 256>>>(xln, wq, bq, nullptr, q,
                                                   TOK, DMODEL, DMODEL, QK_SCALE);
    gemm_nt<0><<<dim3(DMODEL / BN, mtiles), 256>>>(xln, wk, bk, nullptr, k,
                                                   TOK, DMODEL, DMODEL, 1.0f);
    gemm_nt<0><<<dim3(DMODEL / BN, mtiles), 256>>>(xln, wv, bv, nullptr, v,
                                                   TOK, DMODEL, DMODEL, 1.0f);

    // 5) attention
    attn_kernel<<<dim3(NSEQ, BATCH * NHEAD), 128>>>(q, k, v, attn);

    // 6) O projection + residual(hidden_states)
    gemm_nt<2><<<dim3(DMODEL / BN, mtiles), 256>>>(attn, wo, bo, hs, hidden,
                                                   TOK, DMODEL, DMODEL, 1.0f);

    // 7) LN2
    ln_kernel<<<TOK, 256>>>(hidden, ln2_w, ln2_b, h2);

    // 8) FC1 + quick-gelu
    gemm_nt<1><<<dim3(FFDIM / BN, mtiles), 256>>>(h2, fc1_w, fc1_b, nullptr, ff,
                                                  TOK, FFDIM, DMODEL, 1.0f);

    // 9) FC2 + residual(hidden) -> final output
    gemm_nt<2><<<dim3(DMODEL / BN, mtiles), 256>>>(ff, fc2_w, fc2_b, hidden, out,
                                                   TOK, DMODEL, FFDIM, 1.0f);
}

// round 2
// speedup vs baseline: 4.9505x; 4.9505x over previous
#include <cuda_runtime.h>
#include <math.h>
#include <stdint.h>

// Problem constants
#define BATCH   40
#define NSEQ    257
#define DMODEL  1024
#define FFDIM   4096
#define NHEAD   16
#define HDIM    64
#define TOK     (BATCH * NSEQ)      // 10280
#define QK_SCALE 0.125f

// ---------------- scratch ----------------
__device__ float g_xln   [TOK * DMODEL];
__device__ float g_q     [TOK * DMODEL];
__device__ float g_k     [TOK * DMODEL];
__device__ float g_v     [TOK * DMODEL];
__device__ float g_attn  [TOK * DMODEL];
__device__ float g_hidden[TOK * DMODEL];
__device__ float g_h2    [TOK * DMODEL];
__device__ float g_ff    [TOK * FFDIM];

// ---------------- helpers ----------------
__device__ __forceinline__ float warpSum(float v) {
    #pragma unroll
    for (int o = 16; o > 0; o >>= 1) v += __shfl_xor_sync(0xffffffffu, v, o);
    return v;
}

__device__ __forceinline__ uint32_t cvt_tf32(float x) {
    uint32_t o;
    asm("cvt.rna.tf32.f32 %0, %1;" : "=r"(o) : "f"(x));
    return o;
}

__device__ __forceinline__ void mma_tf32(float* d, const uint32_t* a, const uint32_t* b) {
    asm volatile(
        "mma.sync.aligned.m16n8k8.row.col.f32.tf32.tf32.f32 "
        "{%0,%1,%2,%3}, {%4,%5,%6,%7}, {%8,%9}, {%0,%1,%2,%3};"
        : "+f"(d[0]), "+f"(d[1]), "+f"(d[2]), "+f"(d[3])
        : "r"(a[0]), "r"(a[1]), "r"(a[2]), "r"(a[3]), "r"(b[0]), "r"(b[1]));
}

__device__ __forceinline__ uint32_t smem_u32(const void* p) {
    return (uint32_t)__cvta_generic_to_shared(p);
}

// ---------------- LayerNorm ----------------
__global__ void ln_kernel(const float* __restrict__ x,
                          const float* __restrict__ w,
                          const float* __restrict__ b,
                          float* __restrict__ y)
{
    int row = blockIdx.x;
    int tid = threadIdx.x;
    const float* xr = x + (size_t)row * DMODEL;
    float4 v = *(const float4*)&xr[tid * 4];

    float s  = v.x + v.y + v.z + v.w;
    float s2 = v.x * v.x + v.y * v.y + v.z * v.z + v.w * v.w;

    __shared__ float redS[8], redS2[8];
    int lane = tid & 31, wid = tid >> 5;
    s  = warpSum(s);
    s2 = warpSum(s2);
    if (lane == 0) { redS[wid] = s; redS2[wid] = s2; }
    __syncthreads();
    float ts = 0.f, ts2 = 0.f;
    #pragma unroll
    for (int i = 0; i < 8; i++) { ts += redS[i]; ts2 += redS2[i]; }
    float mean = ts * (1.0f / DMODEL);
    float var  = ts2 * (1.0f / DMODEL) - mean * mean;
    float r    = rsqrtf(var + 1e-5f);

    float4 wv = *(const float4*)&w[tid * 4];
    float4 bv = *(const float4*)&b[tid * 4];
    float4 o;
    o.x = (v.x - mean) * r * wv.x + bv.x;
    o.y = (v.y - mean) * r * wv.y + bv.y;
    o.z = (v.z - mean) * r * wv.z + bv.z;
    o.w = (v.w - mean) * r * wv.w + bv.w;
    *(float4*)&(y + (size_t)row * DMODEL)[tid * 4] = o;
}

// ---------------- tf32 tensor-core NT GEMM ----------------
// C[M,N] = epilogue(A[M,K] @ B[N,K]^T + bias)
// MODE 0: *alpha   MODE 1: quick-gelu   MODE 2: + res
#define GBM 128
#define GBN 128
#define GBK 16
#define GP  20        // smem row pitch (floats), 20 => conflict-free frag loads

template<int MODE>
__global__ __launch_bounds__(256)
void gemm_tc(const float* __restrict__ A, const float* __restrict__ B,
             const float* __restrict__ bias, const float* __restrict__ res,
             float* __restrict__ C, int M, int N, int K, float alpha)
{
    __shared__ float As[2][GBM][GP];
    __shared__ float Bs[2][GBN][GP];

    const int tid  = threadIdx.x;
    const int lane = tid & 31;
    const int wid  = tid >> 5;
    const int wm   = (wid & 3) * 32;    // warp M offset within block tile
    const int wn   = (wid >> 2) * 64;   // warp N offset
    const int bm   = blockIdx.y * GBM;
    const int bn   = blockIdx.x * GBN;

    const int r0 = tid >> 2;            // load rows r0 and r0+64
    const int kc = (tid & 3) * 4;       // k column (float4)

    float acc[2][8][4];
    #pragma unroll
    for (int i = 0; i < 2; i++)
        #pragma unroll
        for (int j = 0; j < 8; j++)
            #pragma unroll
            for (int q = 0; q < 4; q++) acc[i][j][q] = 0.f;

    const int ktiles = K / GBK;

    auto load_tile = [&](int kt, int buf) {
        const float* Ab = A + (size_t)bm * K + kt * GBK;
        const float* Bb = B + (size_t)bn * K + kt * GBK;
        #pragma unroll
        for (int i = 0; i < 2; i++) {
            int row = r0 + i * 64;
            uint32_t dst = smem_u32(&As[buf][row][kc]);
            const float* src = Ab + (size_t)row * K + kc;
            int sz = (bm + row < M) ? 16 : 0;
            asm volatile("cp.async.ca.shared.global [%0], [%1], 16, %2;\n"
                         :: "r"(dst), "l"(src), "r"(sz));
        }
        #pragma unroll
        for (int i = 0; i < 2; i++) {
            int row = r0 + i * 64;
            uint32_t dst = smem_u32(&Bs[buf][row][kc]);
            const float* src = Bb + (size_t)row * K + kc;
            asm volatile("cp.async.ca.shared.global [%0], [%1], 16;\n"
                         :: "r"(dst), "l"(src));
        }
        asm volatile("cp.async.commit_group;\n");
    };

    auto compute_tile = [&](int buf) {
        #pragma unroll
        for (int ks = 0; ks < 2; ks++) {
            const int kk = ks * 8 + (lane & 3);
            uint32_t af[2][4];
            uint32_t bf[8][2];
            #pragma unroll
            for (int mt = 0; mt < 2; mt++) {
                int row = wm + mt * 16 + (lane >> 2);
                af[mt][0] = cvt_tf32(As[buf][row    ][kk    ]);
                af[mt][1] = cvt_tf32(As[buf][row + 8][kk    ]);
                af[mt][2] = cvt_tf32(As[buf][row    ][kk + 4]);
                af[mt][3] = cvt_tf32(As[buf][row + 8][kk + 4]);
            }
            #pragma unroll
            for (int nt = 0; nt < 8; nt++) {
                int col = wn + nt * 8 + (lane >> 2);
                bf[nt][0] = cvt_tf32(Bs[buf][col][kk    ]);
                bf[nt][1] = cvt_tf32(Bs[buf][col][kk + 4]);
            }
            #pragma unroll
            for (int mt = 0; mt < 2; mt++)
                #pragma unroll
                for (int nt = 0; nt < 8; nt++)
                    mma_tf32(acc[mt][nt], af[mt], bf[nt]);
        }
    };

    load_tile(0, 0);
    for (int kt = 0; kt < ktiles; kt++) {
        int buf = kt & 1;
        if (kt + 1 < ktiles) {
            load_tile(kt + 1, buf ^ 1);
            asm volatile("cp.async.wait_group 1;\n");
        } else {
            asm volatile("cp.async.wait_group 0;\n");
        }
        __syncthreads();
        compute_tile(buf);
        __syncthreads();
    }

    // epilogue
    #pragma unroll
    for (int mt = 0; mt < 2; mt++) {
        int row0 = bm + wm + mt * 16 + (lane >> 2);
        #pragma unroll
        for (int nt = 0; nt < 8; nt++) {
            int col = bn + wn + nt * 8 + (lane & 3) * 2;
            float b0 = bias[col], b1 = bias[col + 1];
            #pragma unroll
            for (int h = 0; h < 2; h++) {
                int row = row0 + h * 8;
                if (row >= M) continue;
                float v0 = acc[mt][nt][h * 2 + 0] + b0;
                float v1 = acc[mt][nt][h * 2 + 1] + b1;
                if (MODE == 0) {
                    v0 *= alpha; v1 *= alpha;
                } else if (MODE == 1) {
                    v0 = v0 / (1.0f + expf(-1.702f * v0));
                    v1 = v1 / (1.0f + expf(-1.702f * v1));
                } else {
                    const float* rr = &res[(size_t)row * N + col];
                    v0 += rr[0]; v1 += rr[1];
                }
                *(float2*)&C[(size_t)row * N + col] = make_float2(v0, v1);
            }
        }
    }
}

// ---------------- tiled attention: 16 q-rows per block ----------------
#define QT 16
#define KT 64

__global__ __launch_bounds__(256)
void attn_kernel(const float* __restrict__ Q, const float* __restrict__ K,
                 const float* __restrict__ V, float* __restrict__ O)
{
    __shared__ float sc [QT][260];
    __shared__ float Qs [QT][65];
    __shared__ float KVs[KT][65];

    const int qt  = blockIdx.x * QT;
    const int bh  = blockIdx.y;
    const int b   = bh >> 4, h = bh & 15;
    const size_t base = (size_t)b * NSEQ * DMODEL + (size_t)h * HDIM;
    const int tid = threadIdx.x;
    const int q   = tid >> 4;     // 0..15
    const int r   = tid & 15;     // 0..15

    // load Q tile: 16x64 floats = 256 float4, one per thread
    {
        int row = tid >> 4, f4 = tid & 15;
        float4 v = make_float4(0.f, 0.f, 0.f, 0.f);
        if (qt + row < NSEQ)
            v = *(const float4*)&Q[base + (size_t)(qt + row) * DMODEL + f4 * 4];
        Qs[row][f4 * 4 + 0] = v.x; Qs[row][f4 * 4 + 1] = v.y;
        Qs[row][f4 * 4 + 2] = v.z; Qs[row][f4 * 4 + 3] = v.w;
    }

    // ---- scores ----
    for (int kt0 = 0; kt0 < NSEQ; kt0 += KT) {
        __syncthreads();
        #pragma unroll
        for (int i = 0; i < 4; i++) {
            int c = tid + 256 * i;
            int row = c >> 4, f4 = c & 15;
            float4 v = make_float4(0.f, 0.f, 0.f, 0.f);
            if (kt0 + row < NSEQ)
                v = *(const float4*)&K[base + (size_t)(kt0 + row) * DMODEL + f4 * 4];
            KVs[row][f4 * 4 + 0] = v.x; KVs[row][f4 * 4 + 1] = v.y;
            KVs[row][f4 * 4 + 2] = v.z; KVs[row][f4 * 4 + 3] = v.w;
        }
        __syncthreads();
        #pragma unroll
        for (int j = 0; j < 4; j++) {
            int kl = r + 16 * j;
            int kg = kt0 + kl;
            float s = -1e30f;
            if (kg < NSEQ) {
                s = 0.f;
                #pragma unroll
                for (int d = 0; d < HDIM; d++)
                    s = fmaf(Qs[q][d], KVs[kl][d], s);
            }
            if (kg < 260) sc[q][kg] = s;
        }
    }
    __syncthreads();

    // ---- softmax over row q (16-thread group) ----
    float m = -1e30f;
    for (int k = r; k < NSEQ; k += 16) m = fmaxf(m, sc[q][k]);
    #pragma unroll
    for (int o = 8; o > 0; o >>= 1) m = fmaxf(m, __shfl_xor_sync(0xffffffffu, m, o));

    float sum = 0.f;
    for (int k = r; k < NSEQ; k += 16) {
        float e = expf(sc[q][k] - m);
        sc[q][k] = e;
        sum += e;
    }
    #pragma unroll
    for (int o = 8; o > 0; o >>= 1) sum += __shfl_xor_sync(0xffffffffu, sum, o);
    float inv = 1.0f / sum;

    // ---- AV ----
    float accv[4] = {0.f, 0.f, 0.f, 0.f};
    for (int kt0 = 0; kt0 < NSEQ; kt0 += KT) {
        __syncthreads();
        #pragma unroll
        for (int i = 0; i < 4; i++) {
            int c = tid + 256 * i;
            int row = c >> 4, f4 = c & 15;
            float4 v = make_float4(0.f, 0.f, 0.f, 0.f);
            if (kt0 + row < NSEQ)
                v = *(const float4*)&V[base + (size_t)(kt0 + row) * DMODEL + f4 * 4];
            KVs[row][f4 * 4 + 0] = v.x; KVs[row][f4 * 4 + 1] = v.y;
            KVs[row][f4 * 4 + 2] = v.z; KVs[row][f4 * 4 + 3] = v.w;
        }
        __syncthreads();
        int kmax = min(KT, NSEQ - kt0);
        for (int kl = 0; kl < kmax; kl++) {
            float p = sc[q][kt0 + kl];
            #pragma unroll
            for (int j = 0; j < 4; j++)
                accv[j] = fmaf(p, KVs[kl][r + 16 * j], accv[j]);
        }
    }
    if (qt + q < NSEQ) {
        #pragma unroll
        for (int j = 0; j < 4; j++)
            O[base + (size_t)(qt + q) * DMODEL + r + 16 * j] = accv[j] * inv;
    }
}

// ---------------- launch ----------------
extern "C" void kernel_launch(void* const* d_in, const int* in_sizes, int n_in,
                              void* d_out, int out_size)
{
    const float* hs     = (const float*)d_in[0];
    const float* ln1_w  = (const float*)d_in[1];
    const float* ln1_b  = (const float*)d_in[2];
    const float* wq     = (const float*)d_in[3];
    const float* bq     = (const float*)d_in[4];
    const float* wk     = (const float*)d_in[5];
    const float* bk     = (const float*)d_in[6];
    const float* wv     = (const float*)d_in[7];
    const float* bv     = (const float*)d_in[8];
    const float* wo     = (const float*)d_in[9];
    const float* bo     = (const float*)d_in[10];
    const float* ln2_w  = (const float*)d_in[11];
    const float* ln2_b  = (const float*)d_in[12];
    const float* fc1_w  = (const float*)d_in[13];
    const float* fc1_b  = (const float*)d_in[14];
    const float* fc2_w  = (const float*)d_in[15];
    const float* fc2_b  = (const float*)d_in[16];
    float* out          = (float*)d_out;

    static float *xln = nullptr, *q = nullptr, *k = nullptr, *v = nullptr,
                 *attn = nullptr, *hidden = nullptr, *h2 = nullptr, *ff = nullptr;
    if (!xln) {
        cudaGetSymbolAddress((void**)&xln,    g_xln);
        cudaGetSymbolAddress((void**)&q,      g_q);
        cudaGetSymbolAddress((void**)&k,      g_k);
        cudaGetSymbolAddress((void**)&v,      g_v);
        cudaGetSymbolAddress((void**)&attn,   g_attn);
        cudaGetSymbolAddress((void**)&hidden, g_hidden);
        cudaGetSymbolAddress((void**)&h2,     g_h2);
        cudaGetSymbolAddress((void**)&ff,     g_ff);
    }

    const int mtiles = (TOK + GBM - 1) / GBM;   // 81

    // 1) LN1
    ln_kernel<<<TOK, 256>>>(hs, ln1_w, ln1_b, xln);

    // 2-4) QKV projections (Q pre-scaled)
    gemm_tc<0><<<dim3(DMODEL / GBN, mtiles), 256>>>(xln, wq, bq, nullptr, q,
                                                    TOK, DMODEL, DMODEL, QK_SCALE);
    gemm_tc<0><<<dim3(DMODEL / GBN, mtiles), 256>>>(xln, wk, bk, nullptr, k,
                                                    TOK, DMODEL, DMODEL, 1.0f);
    gemm_tc<0><<<dim3(DMODEL / GBN, mtiles), 256>>>(xln, wv, bv, nullptr, v,
                                                    TOK, DMODEL, DMODEL, 1.0f);

    // 5) attention
    attn_kernel<<<dim3((NSEQ + QT - 1) / QT, BATCH * NHEAD), 256>>>(q, k, v, attn);

    // 6) O projection + residual
    gemm_tc<2><<<dim3(DMODEL / GBN, mtiles), 256>>>(attn, wo, bo, hs, hidden,
                                                    TOK, DMODEL, DMODEL, 1.0f);

    // 7) LN2
    ln_kernel<<<TOK, 256>>>(hidden, ln2_w, ln2_b, h2);

    // 8) FC1 + quick-gelu
    gemm_tc<1><<<dim3(FFDIM / GBN, mtiles), 256>>>(h2, fc1_w, fc1_b, nullptr, ff,
                                                   TOK, FFDIM, DMODEL, 1.0f);

    // 9) FC2 + residual -> output
    gemm_tc<2><<<dim3(DMODEL / GBN, mtiles), 256>>>(ff, fc2_w, fc2_b, hidden, out,
                                                    TOK, DMODEL, FFDIM, 1.0f);
}

// round 3
// speedup vs baseline: 5.8853x; 1.1888x over previous
#include <cuda_runtime.h>
#include <math.h>
#include <stdint.h>

// Problem constants
#define BATCH   40
#define NSEQ    257
#define DMODEL  1024
#define FFDIM   4096
#define NHEAD   16
#define HDIM    64
#define TOK     (BATCH * NSEQ)      // 10280
#define QK_SCALE 0.125f

// ---------------- scratch ----------------
__device__ float g_xln   [TOK * DMODEL];
__device__ float g_q     [TOK * DMODEL];
__device__ float g_k     [TOK * DMODEL];
__device__ float g_v     [TOK * DMODEL];
__device__ float g_attn  [TOK * DMODEL];
__device__ float g_hidden[TOK * DMODEL];
__device__ float g_h2    [TOK * DMODEL];
__device__ float g_ff    [TOK * FFDIM];
// rounded weight copies
__device__ float g_wqr [DMODEL * DMODEL];
__device__ float g_wkr [DMODEL * DMODEL];
__device__ float g_wvr [DMODEL * DMODEL];
__device__ float g_wor [DMODEL * DMODEL];
__device__ float g_fc1r[FFDIM * DMODEL];
__device__ float g_fc2r[DMODEL * FFDIM];

// ---------------- helpers ----------------
__device__ __forceinline__ float warpSum(float v) {
    #pragma unroll
    for (int o = 16; o > 0; o >>= 1) v += __shfl_xor_sync(0xffffffffu, v, o);
    return v;
}
__device__ __forceinline__ uint32_t cvt_tf32(float x) {
    uint32_t o;
    asm("cvt.rna.tf32.f32 %0, %1;" : "=r"(o) : "f"(x));
    return o;
}
__device__ __forceinline__ float round_tf32(float x) {
    return __uint_as_float(cvt_tf32(x));
}
__device__ __forceinline__ void mma_tf32(float* d, const uint32_t* a, const uint32_t* b) {
    asm volatile(
        "mma.sync.aligned.m16n8k8.row.col.f32.tf32.tf32.f32 "
        "{%0,%1,%2,%3}, {%4,%5,%6,%7}, {%8,%9}, {%0,%1,%2,%3};"
        : "+f"(d[0]), "+f"(d[1]), "+f"(d[2]), "+f"(d[3])
        : "r"(a[0]), "r"(a[1]), "r"(a[2]), "r"(a[3]), "r"(b[0]), "r"(b[1]));
}
__device__ __forceinline__ uint32_t smem_u32(const void* p) {
    return (uint32_t)__cvta_generic_to_shared(p);
}
__device__ __forceinline__ uint32_t fbits(float x) { return __float_as_uint(x); }

// ---------------- weight rounding ----------------
__global__ void round_kernel(const float4* __restrict__ in, float4* __restrict__ out, int n4)
{
    int i = blockIdx.x * blockDim.x + threadIdx.x;
    if (i < n4) {
        float4 v = in[i];
        v.x = round_tf32(v.x); v.y = round_tf32(v.y);
        v.z = round_tf32(v.z); v.w = round_tf32(v.w);
        out[i] = v;
    }
}

// ---------------- LayerNorm (optionally rounds output to tf32) ----------------
template<bool RND>
__global__ void ln_kernel(const float* __restrict__ x,
                          const float* __restrict__ w,
                          const float* __restrict__ b,
                          float* __restrict__ y)
{
    int row = blockIdx.x;
    int tid = threadIdx.x;
    const float* xr = x + (size_t)row * DMODEL;
    float4 v = *(const float4*)&xr[tid * 4];

    float s  = v.x + v.y + v.z + v.w;
    float s2 = v.x * v.x + v.y * v.y + v.z * v.z + v.w * v.w;

    __shared__ float redS[8], redS2[8];
    int lane = tid & 31, wid = tid >> 5;
    s  = warpSum(s);
    s2 = warpSum(s2);
    if (lane == 0) { redS[wid] = s; redS2[wid] = s2; }
    __syncthreads();
    float ts = 0.f, ts2 = 0.f;
    #pragma unroll
    for (int i = 0; i < 8; i++) { ts += redS[i]; ts2 += redS2[i]; }
    float mean = ts * (1.0f / DMODEL);
    float var  = ts2 * (1.0f / DMODEL) - mean * mean;
    float r    = rsqrtf(var + 1e-5f);

    float4 wv = *(const float4*)&w[tid * 4];
    float4 bv = *(const float4*)&b[tid * 4];
    float4 o;
    o.x = (v.x - mean) * r * wv.x + bv.x;
    o.y = (v.y - mean) * r * wv.y + bv.y;
    o.z = (v.z - mean) * r * wv.z + bv.z;
    o.w = (v.w - mean) * r * wv.w + bv.w;
    if (RND) {
        o.x = round_tf32(o.x); o.y = round_tf32(o.y);
        o.z = round_tf32(o.z); o.w = round_tf32(o.w);
    }
    *(float4*)&(y + (size_t)row * DMODEL)[tid * 4] = o;
}

// ---------------- tf32 tensor-core NT GEMM ----------------
// C[M,N] = epilogue(A[M,K] @ B[N,K]^T + bias)
// operands pre-rounded to tf32 bit patterns. MODE 0: *alpha  1: quick-gelu  2: +res
// RND: round output to tf32 (when C feeds another mma as operand)
#define GBM 128
#define GBN 128
#define GBK 16
#define GP  20
#define STG 3

template<int MODE, bool RND>
__global__ __launch_bounds__(256, 2)
void gemm_tc(const float* __restrict__ A, const float* __restrict__ B,
             const float* __restrict__ bias, const float* __restrict__ res,
             float* __restrict__ C, int M, int N, int K, float alpha)
{
    __shared__ float As[STG][GBM][GP];
    __shared__ float Bs[STG][GBN][GP];

    const int tid  = threadIdx.x;
    const int lane = tid & 31;
    const int wid  = tid >> 5;
    const int wm   = (wid & 3) * 32;
    const int wn   = (wid >> 2) * 64;
    const int bm   = blockIdx.y * GBM;
    const int bn   = blockIdx.x * GBN;

    const int r0 = tid >> 2;
    const int kc = (tid & 3) * 4;

    float acc[2][8][4];
    #pragma unroll
    for (int i = 0; i < 2; i++)
        #pragma unroll
        for (int j = 0; j < 8; j++)
            #pragma unroll
            for (int q = 0; q < 4; q++) acc[i][j][q] = 0.f;

    const int ktiles = K / GBK;

    auto load_tile = [&](int kt, int slot) {
        const float* Ab = A + (size_t)bm * K + kt * GBK;
        const float* Bb = B + (size_t)bn * K + kt * GBK;
        #pragma unroll
        for (int i = 0; i < 2; i++) {
            int row = r0 + i * 64;
            uint32_t dst = smem_u32(&As[slot][row][kc]);
            const float* src = Ab + (size_t)row * K + kc;
            int sz = (bm + row < M) ? 16 : 0;
            asm volatile("cp.async.ca.shared.global [%0], [%1], 16, %2;\n"
                         :: "r"(dst), "l"(src), "r"(sz));
        }
        #pragma unroll
        for (int i = 0; i < 2; i++) {
            int row = r0 + i * 64;
            uint32_t dst = smem_u32(&Bs[slot][row][kc]);
            const float* src = Bb + (size_t)row * K + kc;
            asm volatile("cp.async.ca.shared.global [%0], [%1], 16;\n"
                         :: "r"(dst), "l"(src));
        }
        asm volatile("cp.async.commit_group;\n");
    };

    auto compute_tile = [&](int slot) {
        #pragma unroll
        for (int ks = 0; ks < 2; ks++) {
            const int kk = ks * 8 + (lane & 3);
            uint32_t af[2][4];
            uint32_t bf[8][2];
            #pragma unroll
            for (int mt = 0; mt < 2; mt++) {
                int row = wm + mt * 16 + (lane >> 2);
                af[mt][0] = fbits(As[slot][row    ][kk    ]);
                af[mt][1] = fbits(As[slot][row + 8][kk    ]);
                af[mt][2] = fbits(As[slot][row    ][kk + 4]);
                af[mt][3] = fbits(As[slot][row + 8][kk + 4]);
            }
            #pragma unroll
            for (int nt = 0; nt < 8; nt++) {
                int col = wn + nt * 8 + (lane >> 2);
                bf[nt][0] = fbits(Bs[slot][col][kk    ]);
                bf[nt][1] = fbits(Bs[slot][col][kk + 4]);
            }
            #pragma unroll
            for (int mt = 0; mt < 2; mt++)
                #pragma unroll
                for (int nt = 0; nt < 8; nt++)
                    mma_tf32(acc[mt][nt], af[mt], bf[nt]);
        }
    };

    // prologue: fill STG-1 stages
    #pragma unroll
    for (int s = 0; s < STG - 1; s++)
        if (s < ktiles) load_tile(s, s);

    int cur = 0, pre = STG - 1;
    for (int kt = 0; kt < ktiles; kt++) {
        asm volatile("cp.async.wait_group %0;\n" :: "n"(STG - 2));
        __syncthreads();
        if (kt + STG - 1 < ktiles) load_tile(kt + STG - 1, pre);
        compute_tile(cur);
        cur = (cur + 1 == STG) ? 0 : cur + 1;
        pre = (pre + 1 == STG) ? 0 : pre + 1;
    }

    // epilogue
    #pragma unroll
    for (int mt = 0; mt < 2; mt++) {
        int row0 = bm + wm + mt * 16 + (lane >> 2);
        #pragma unroll
        for (int nt = 0; nt < 8; nt++) {
            int col = bn + wn + nt * 8 + (lane & 3) * 2;
            float b0 = bias[col], b1 = bias[col + 1];
            #pragma unroll
            for (int h = 0; h < 2; h++) {
                int row = row0 + h * 8;
                if (row >= M) continue;
                float v0 = acc[mt][nt][h * 2 + 0] + b0;
                float v1 = acc[mt][nt][h * 2 + 1] + b1;
                if (MODE == 0) {
                    v0 *= alpha; v1 *= alpha;
                } else if (MODE == 1) {
                    v0 = v0 / (1.0f + expf(-1.702f * v0));
                    v1 = v1 / (1.0f + expf(-1.702f * v1));
                } else {
                    const float* rr = &res[(size_t)row * N + col];
                    v0 += rr[0]; v1 += rr[1];
                }
                if (RND) { v0 = round_tf32(v0); v1 = round_tf32(v1); }
                *(float2*)&C[(size_t)row * N + col] = make_float2(v0, v1);
            }
        }
    }
}

// ---------------- tensor-core attention ----------------
// per (b,h, 64-q-tile): S = Q K^T (tf32 mma), softmax (P rounded tf32), O = P V
#define AQT 64
#define AKT 64
#define NKT 5            // ceil(257/64)
#define SP  332          // score pitch (floats); 332%32==12 -> conflict-free frags
#define QP  65

#define ATT_SMEM (AQT*QP*4 + AKT*QP*4 + AQT*SP*4 + AQT*4)

__global__ __launch_bounds__(256)
void attn_tc(const float* __restrict__ Q, const float* __restrict__ K,
             const float* __restrict__ V, float* __restrict__ O)
{
    extern __shared__ __align__(16) char smraw[];
    float (*Qs)[QP]  = (float(*)[QP])smraw;
    float (*KVs)[QP] = (float(*)[QP])(smraw + AQT * QP * 4);
    float (*Ss)[SP]  = (float(*)[SP])(smraw + AQT * QP * 4 + AKT * QP * 4);
    float* sinv      = (float*)(smraw + AQT * QP * 4 + AKT * QP * 4 + AQT * SP * 4);

    const int qt  = blockIdx.x * AQT;
    const int bh  = blockIdx.y;
    const int b   = bh >> 4, h = bh & 15;
    const size_t base = (size_t)b * NSEQ * DMODEL + (size_t)h * HDIM;
    const int tid  = threadIdx.x;
    const int lane = tid & 31;
    const int wid  = tid >> 5;
    const int wm   = (wid & 3) * 16;   // 4 warps over q-rows
    const int wn   = (wid >> 2) * 32;  // 2 warps over cols

    // load Q tile [64 q][64 d]
    #pragma unroll
    for (int i = 0; i < 4; i++) {
        int idx = tid + 256 * i;
        int row = idx >> 4, f4 = idx & 15;
        float4 v = make_float4(0.f, 0.f, 0.f, 0.f);
        if (qt + row < NSEQ)
            v = *(const float4*)&Q[base + (size_t)(qt + row) * DMODEL + f4 * 4];
        Qs[row][f4*4+0] = v.x; Qs[row][f4*4+1] = v.y;
        Qs[row][f4*4+2] = v.z; Qs[row][f4*4+3] = v.w;
    }

    // ---- phase 1: scores ----
    for (int t = 0; t < NKT; t++) {
        int kt0 = t * AKT;
        __syncthreads();
        #pragma unroll
        for (int i = 0; i < 4; i++) {
            int idx = tid + 256 * i;
            int row = idx >> 4, f4 = idx & 15;
            float4 v = make_float4(0.f, 0.f, 0.f, 0.f);
            if (kt0 + row < NSEQ)
                v = *(const float4*)&K[base + (size_t)(kt0 + row) * DMODEL + f4 * 4];
            KVs[row][f4*4+0] = v.x; KVs[row][f4*4+1] = v.y;
            KVs[row][f4*4+2] = v.z; KVs[row][f4*4+3] = v.w;
        }
        __syncthreads();

        float accS[4][4];
        #pragma unroll
        for (int nt = 0; nt < 4; nt++)
            #pragma unroll
            for (int q = 0; q < 4; q++) accS[nt][q] = 0.f;

        #pragma unroll
        for (int ks = 0; ks < 8; ks++) {
            int kk = ks * 8 + (lane & 3);
            uint32_t af[4];
            int row = wm + (lane >> 2);
            af[0] = fbits(Qs[row    ][kk    ]);
            af[1] = fbits(Qs[row + 8][kk    ]);
            af[2] = fbits(Qs[row    ][kk + 4]);
            af[3] = fbits(Qs[row + 8][kk + 4]);
            #pragma unroll
            for (int nt = 0; nt < 4; nt++) {
                int col = wn + nt * 8 + (lane >> 2);
                uint32_t bf[2];
                bf[0] = fbits(KVs[col][kk    ]);
                bf[1] = fbits(KVs[col][kk + 4]);
                mma_tf32(accS[nt], af, bf);
            }
        }
        // store S fragment
        int row = wm + (lane >> 2);
        #pragma unroll
        for (int nt = 0; nt < 4; nt++) {
            int col = kt0 + wn + nt * 8 + (lane & 3) * 2;
            Ss[row    ][col    ] = accS[nt][0];
            Ss[row    ][col + 1] = accS[nt][1];
            Ss[row + 8][col    ] = accS[nt][2];
            Ss[row + 8][col + 1] = accS[nt][3];
        }
    }
    __syncthreads();

    // ---- softmax: 4 threads per row ----
    {
        int row = tid >> 2, r = tid & 3;
        float m = -1e30f;
        for (int k = r; k < NSEQ; k += 4) m = fmaxf(m, Ss[row][k]);
        m = fmaxf(m, __shfl_xor_sync(0xffffffffu, m, 1));
        m = fmaxf(m, __shfl_xor_sync(0xffffffffu, m, 2));
        float sum = 0.f;
        for (int k = r; k < NKT * AKT; k += 4) {
            if (k < NSEQ) {
                float e = __expf(Ss[row][k] - m);
                Ss[row][k] = round_tf32(e);
                sum += e;
            } else {
                Ss[row][k] = 0.f;
            }
        }
        sum += __shfl_xor_sync(0xffffffffu, sum, 1);
        sum += __shfl_xor_sync(0xffffffffu, sum, 2);
        if (r == 0) sinv[row] = 1.0f / sum;
    }

    // ---- phase 2: O = P V ----
    float accO[4][4];
    #pragma unroll
    for (int nt = 0; nt < 4; nt++)
        #pragma unroll
        for (int q = 0; q < 4; q++) accO[nt][q] = 0.f;

    for (int t = 0; t < NKT; t++) {
        int kt0 = t * AKT;
        __syncthreads();
        // load V tile transposed: KVs[d][seq]
        #pragma unroll
        for (int i = 0; i < 4; i++) {
            int idx = tid + 256 * i;
            int row = idx >> 4, f4 = idx & 15;
            float4 v = make_float4(0.f, 0.f, 0.f, 0.f);
            if (kt0 + row < NSEQ)
                v = *(const float4*)&V[base + (size_t)(kt0 + row) * DMODEL + f4 * 4];
            KVs[f4*4+0][row] = v.x; KVs[f4*4+1][row] = v.y;
            KVs[f4*4+2][row] = v.z; KVs[f4*4+3][row] = v.w;
        }
        __syncthreads();

        #pragma unroll
        for (int ks = 0; ks < 8; ks++) {
            int kk = ks * 8 + (lane & 3);
            uint32_t af[4];
            int row = wm + (lane >> 2);
            af[0] = fbits(Ss[row    ][kt0 + kk    ]);
            af[1] = fbits(Ss[row + 8][kt0 + kk    ]);
            af[2] = fbits(Ss[row    ][kt0 + kk + 4]);
            af[3] = fbits(Ss[row + 8][kt0 + kk + 4]);
            #pragma unroll
            for (int nt = 0; nt < 4; nt++) {
                int col = wn + nt * 8 + (lane >> 2);
                uint32_t bf[2];
                bf[0] = fbits(KVs[col][kk    ]);
                bf[1] = fbits(KVs[col][kk + 4]);
                mma_tf32(accO[nt], af, bf);
            }
        }
    }

    // epilogue: scale by 1/sum, round (feeds O-proj), write
    {
        int row = wm + (lane >> 2);
        float i0 = sinv[row], i1 = sinv[row + 8];
        #pragma unroll
        for (int nt = 0; nt < 4; nt++) {
            int col = wn + nt * 8 + (lane & 3) * 2;
            if (qt + row < NSEQ) {
                float2 o0 = make_float2(round_tf32(accO[nt][0] * i0),
                                        round_tf32(accO[nt][1] * i0));
                *(float2*)&O[base + (size_t)(qt + row) * DMODEL + col] = o0;
            }
            if (qt + row + 8 < NSEQ) {
                float2 o1 = make_float2(round_tf32(accO[nt][2] * i1),
                                        round_tf32(accO[nt][3] * i1));
                *(float2*)&O[base + (size_t)(qt + row + 8) * DMODEL + col] = o1;
            }
        }
    }
}

// ---------------- launch ----------------
extern "C" void kernel_launch(void* const* d_in, const int* in_sizes, int n_in,
                              void* d_out, int out_size)
{
    const float* hs     = (const float*)d_in[0];
    const float* ln1_w  = (const float*)d_in[1];
    const float* ln1_b  = (const float*)d_in[2];
    const float* wq     = (const float*)d_in[3];
    const float* bq     = (const float*)d_in[4];
    const float* wk     = (const float*)d_in[5];
    const float* bk     = (const float*)d_in[6];
    const float* wv     = (const float*)d_in[7];
    const float* bv     = (const float*)d_in[8];
    const float* wo     = (const float*)d_in[9];
    const float* bo     = (const float*)d_in[10];
    const float* ln2_w  = (const float*)d_in[11];
    const float* ln2_b  = (const float*)d_in[12];
    const float* fc1_w  = (const float*)d_in[13];
    const float* fc1_b  = (const float*)d_in[14];
    const float* fc2_w  = (const float*)d_in[15];
    const float* fc2_b  = (const float*)d_in[16];
    float* out          = (float*)d_out;

    static float *xln=nullptr,*q=nullptr,*k=nullptr,*v=nullptr,*attn=nullptr,
                 *hidden=nullptr,*h2=nullptr,*ff=nullptr,
                 *wqr=nullptr,*wkr=nullptr,*wvr=nullptr,*wor=nullptr,
                 *fc1r=nullptr,*fc2r=nullptr;
    if (!xln) {
        cudaGetSymbolAddress((void**)&xln,    g_xln);
        cudaGetSymbolAddress((void**)&q,      g_q);
        cudaGetSymbolAddress((void**)&k,      g_k);
        cudaGetSymbolAddress((void**)&v,      g_v);
        cudaGetSymbolAddress((void**)&attn,   g_attn);
        cudaGetSymbolAddress((void**)&hidden, g_hidden);
        cudaGetSymbolAddress((void**)&h2,     g_h2);
        cudaGetSymbolAddress((void**)&ff,     g_ff);
        cudaGetSymbolAddress((void**)&wqr,    g_wqr);
        cudaGetSymbolAddress((void**)&wkr,    g_wkr);
        cudaGetSymbolAddress((void**)&wvr,    g_wvr);
        cudaGetSymbolAddress((void**)&wor,    g_wor);
        cudaGetSymbolAddress((void**)&fc1r,   g_fc1r);
        cudaGetSymbolAddress((void**)&fc2r,   g_fc2r);
        cudaFuncSetAttribute(attn_tc, cudaFuncAttributeMaxDynamicSharedMemorySize, ATT_SMEM);
    }

    const int mtiles = (TOK + GBM - 1) / GBM;   // 81
    const int n4w = DMODEL * DMODEL / 4;        // 262144
    const int n4f = FFDIM * DMODEL / 4;         // 1048576

    // 0) round weights to tf32
    round_kernel<<<n4w / 256, 256>>>((const float4*)wq,    (float4*)wqr,  n4w);
    round_kernel<<<n4w / 256, 256>>>((const float4*)wk,    (float4*)wkr,  n4w);
    round_kernel<<<n4w / 256, 256>>>((const float4*)wv,    (float4*)wvr,  n4w);
    round_kernel<<<n4w / 256, 256>>>((const float4*)wo,    (float4*)wor,  n4w);
    round_kernel<<<n4f / 256, 256>>>((const float4*)fc1_w, (float4*)fc1r, n4f);
    round_kernel<<<n4f / 256, 256>>>((const float4*)fc2_w, (float4*)fc2r, n4f);

    // 1) LN1 (rounded -> feeds QKV mma)
    ln_kernel<true><<<TOK, 256>>>(hs, ln1_w, ln1_b, xln);

    // 2-4) QKV projections (rounded outputs -> feed attention mma; Q pre-scaled)
    gemm_tc<0,true><<<dim3(DMODEL/GBN, mtiles), 256>>>(xln, wqr, bq, nullptr, q,
                                                       TOK, DMODEL, DMODEL, QK_SCALE);
    gemm_tc<0,true><<<dim3(DMODEL/GBN, mtiles), 256>>>(xln, wkr, bk, nullptr, k,
                                                       TOK, DMODEL, DMODEL, 1.0f);
    gemm_tc<0,true><<<dim3(DMODEL/GBN, mtiles), 256>>>(xln, wvr, bv, nullptr, v,
                                                       TOK, DMODEL, DMODEL, 1.0f);

    // 5) attention (tensor cores)
    attn_tc<<<dim3((NSEQ + AQT - 1)/AQT, BATCH*NHEAD), 256, ATT_SMEM>>>(q, k, v, attn);

    // 6) O projection + residual (fp32 out)
    gemm_tc<2,false><<<dim3(DMODEL/GBN, mtiles), 256>>>(attn, wor, bo, hs, hidden,
                                                        TOK, DMODEL, DMODEL, 1.0f);

    // 7) LN2 (rounded -> feeds FC1 mma)
    ln_kernel<true><<<TOK, 256>>>(hidden, ln2_w, ln2_b, h2);

    // 8) FC1 + quick-gelu (rounded -> feeds FC2 mma)
    gemm_tc<1,true><<<dim3(FFDIM/GBN, mtiles), 256>>>(h2, fc1r, fc1_b, nullptr, ff,
                                                      TOK, FFDIM, DMODEL, 1.0f);

    // 9) FC2 + residual -> output (fp32)
    gemm_tc<2,false><<<dim3(DMODEL/GBN, mtiles), 256>>>(ff, fc2r, fc2_b, hidden, out,
                                                        TOK, DMODEL, FFDIM, 1.0f);
}

// round 5
// speedup vs baseline: 11.2992x; 1.9199x over previous
#include <cuda_runtime.h>
#include <cuda_fp16.h>
#include <math.h>
#include <stdint.h>

// Problem constants
#define BATCH   40
#define NSEQ    257
#define DMODEL  1024
#define FFDIM   4096
#define NHEAD   16
#define HDIM    64
#define TOK     (BATCH * NSEQ)      // 10280
#define QK_SCALE 0.125f

// ---------------- scratch ----------------
__device__ __half g_xln_h [TOK * DMODEL];
__device__ __half g_q_h   [TOK * DMODEL];
__device__ __half g_k_h   [TOK * DMODEL];
__device__ __half g_v_h   [TOK * DMODEL];
__device__ __half g_attn_h[TOK * DMODEL];
__device__ float  g_hidden[TOK * DMODEL];
__device__ __half g_h2_h  [TOK * DMODEL];
__device__ __half g_ff_h  [TOK * FFDIM];
__device__ __half g_wq_h  [DMODEL * DMODEL];
__device__ __half g_wk_h  [DMODEL * DMODEL];
__device__ __half g_wv_h  [DMODEL * DMODEL];
__device__ __half g_wo_h  [DMODEL * DMODEL];
__device__ __half g_fc1_h [FFDIM * DMODEL];
__device__ __half g_fc2_h [DMODEL * FFDIM];

// ---------------- helpers ----------------
__device__ __forceinline__ float warpSum(float v) {
    #pragma unroll
    for (int o = 16; o > 0; o >>= 1) v += __shfl_xor_sync(0xffffffffu, v, o);
    return v;
}
__device__ __forceinline__ void mma_f16(float* d, const uint32_t* a, const uint32_t* b) {
    asm volatile(
        "mma.sync.aligned.m16n8k16.row.col.f32.f16.f16.f32 "
        "{%0,%1,%2,%3}, {%4,%5,%6,%7}, {%8,%9}, {%0,%1,%2,%3};"
        : "+f"(d[0]), "+f"(d[1]), "+f"(d[2]), "+f"(d[3])
        : "r"(a[0]), "r"(a[1]), "r"(a[2]), "r"(a[3]), "r"(b[0]), "r"(b[1]));
}
__device__ __forceinline__ uint32_t smem_u32(const void* p) {
    return (uint32_t)__cvta_generic_to_shared(p);
}
__device__ __forceinline__ uint32_t ld_u32(const __half* p) {
    return *(const uint32_t*)p;
}
__device__ __forceinline__ uint32_t packh2(float a, float b) {
    __half2 h = __floats2half2_rn(a, b);
    return *(uint32_t*)&h;
}

// ---------------- weight conversion: fp32 -> fp16 ----------------
__global__ void cvt_half_kernel(const float4* __restrict__ in, uint2* __restrict__ out, int n4)
{
    int i = blockIdx.x * blockDim.x + threadIdx.x;
    if (i < n4) {
        float4 v = in[i];
        uint2 o;
        o.x = packh2(v.x, v.y);
        o.y = packh2(v.z, v.w);
        out[i] = o;
    }
}

// ---------------- LayerNorm -> half out ----------------
__global__ void ln_kernel(const float* __restrict__ x,
                          const float* __restrict__ w,
                          const float* __restrict__ b,
                          __half* __restrict__ y)
{
    int row = blockIdx.x;
    int tid = threadIdx.x;
    const float* xr = x + (size_t)row * DMODEL;
    float4 v = *(const float4*)&xr[tid * 4];

    float s  = v.x + v.y + v.z + v.w;
    float s2 = v.x * v.x + v.y * v.y + v.z * v.z + v.w * v.w;

    __shared__ float redS[8], redS2[8];
    int lane = tid & 31, wid = tid >> 5;
    s  = warpSum(s);
    s2 = warpSum(s2);
    if (lane == 0) { redS[wid] = s; redS2[wid] = s2; }
    __syncthreads();
    float ts = 0.f, ts2 = 0.f;
    #pragma unroll
    for (int i = 0; i < 8; i++) { ts += redS[i]; ts2 += redS2[i]; }
    float mean = ts * (1.0f / DMODEL);
    float var  = ts2 * (1.0f / DMODEL) - mean * mean;
    float r    = rsqrtf(var + 1e-5f);

    float4 wv = *(const float4*)&w[tid * 4];
    float4 bv = *(const float4*)&b[tid * 4];
    float o0 = (v.x - mean) * r * wv.x + bv.x;
    float o1 = (v.y - mean) * r * wv.y + bv.y;
    float o2 = (v.z - mean) * r * wv.z + bv.z;
    float o3 = (v.w - mean) * r * wv.w + bv.w;
    uint2 st;
    st.x = packh2(o0, o1);
    st.y = packh2(o2, o3);
    *(uint2*)&y[(size_t)row * DMODEL + tid * 4] = st;
}

// ---------------- fp16 tensor-core NT GEMM ----------------
// C[M,N] = epilogue(A[M,K] @ B[N,K]^T + bias)
// A,B half; bias/res fp32. MODE 0: (acc+bias)*alpha -> half
//                          MODE 1: quick-gelu       -> half
//                          MODE 2: acc+bias+res     -> float
#define GBM 128
#define GBN 128
#define GBK 32      // halves per K-tile
#define PH  40      // smem pitch in halves (80B, conflict-free frags)
#define STG 3

template<int MODE>
__device__ __forceinline__ void gemm_body(
    const __half* __restrict__ A, const __half* __restrict__ B,
    const float* __restrict__ bias, const float* __restrict__ res,
    void* __restrict__ Cv, int M, int N, int K, float alpha, int bm, int bn)
{
    __shared__ __half As[STG][GBM][PH];
    __shared__ __half Bs[STG][GBN][PH];

    const int tid  = threadIdx.x;
    const int lane = tid & 31;
    const int wid  = tid >> 5;
    const int wm   = (wid & 3) * 32;
    const int wn   = (wid >> 2) * 64;

    float acc[2][8][4];
    #pragma unroll
    for (int i = 0; i < 2; i++)
        #pragma unroll
        for (int j = 0; j < 8; j++)
            #pragma unroll
            for (int q = 0; q < 4; q++) acc[i][j][q] = 0.f;

    const int ktiles = K / GBK;

    auto load_tile = [&](int kt, int s) {
        #pragma unroll
        for (int i = 0; i < 2; i++) {
            int idx = tid + 256 * i;
            int row = idx >> 2, ch = idx & 3;
            uint32_t dst = smem_u32(&As[s][row][ch * 8]);
            const __half* src = A + (size_t)(bm + row) * K + kt * GBK + ch * 8;
            int sz = (bm + row < M) ? 16 : 0;
            asm volatile("cp.async.ca.shared.global [%0], [%1], 16, %2;"
                         :: "r"(dst), "l"(src), "r"(sz));
        }
        #pragma unroll
        for (int i = 0; i < 2; i++) {
            int idx = tid + 256 * i;
            int row = idx >> 2, ch = idx & 3;
            uint32_t dst = smem_u32(&Bs[s][row][ch * 8]);
            const __half* src = B + (size_t)(bn + row) * K + kt * GBK + ch * 8;
            asm volatile("cp.async.ca.shared.global [%0], [%1], 16;"
                         :: "r"(dst), "l"(src));
        }
        asm volatile("cp.async.commit_group;");
    };

    auto compute_tile = [&](int s) {
        #pragma unroll
        for (int ks = 0; ks < 2; ks++) {
            const int kk = ks * 16 + (lane & 3) * 2;
            uint32_t af[2][4];
            uint32_t bf[8][2];
            #pragma unroll
            for (int mt = 0; mt < 2; mt++) {
                int row = wm + mt * 16 + (lane >> 2);
                af[mt][0] = ld_u32(&As[s][row    ][kk    ]);
                af[mt][1] = ld_u32(&As[s][row + 8][kk    ]);
                af[mt][2] = ld_u32(&As[s][row    ][kk + 8]);
                af[mt][3] = ld_u32(&As[s][row + 8][kk + 8]);
            }
            #pragma unroll
            for (int nt = 0; nt < 8; nt++) {
                int col = wn + nt * 8 + (lane >> 2);
                bf[nt][0] = ld_u32(&Bs[s][col][kk    ]);
                bf[nt][1] = ld_u32(&Bs[s][col][kk + 8]);
            }
            #pragma unroll
            for (int mt = 0; mt < 2; mt++)
                #pragma unroll
                for (int nt = 0; nt < 8; nt++)
                    mma_f16(acc[mt][nt], af[mt], bf[nt]);
        }
    };

    #pragma unroll
    for (int s = 0; s < STG - 1; s++)
        if (s < ktiles) load_tile(s, s);

    int cur = 0, pre = STG - 1;
    for (int kt = 0; kt < ktiles; kt++) {
        asm volatile("cp.async.wait_group %0;" :: "n"(STG - 2));
        __syncthreads();
        if (kt + STG - 1 < ktiles) load_tile(kt + STG - 1, pre);
        compute_tile(cur);
        cur = (cur + 1 == STG) ? 0 : cur + 1;
        pre = (pre + 1 == STG) ? 0 : pre + 1;
    }

    // epilogue
    #pragma unroll
    for (int mt = 0; mt < 2; mt++) {
        int row0 = bm + wm + mt * 16 + (lane >> 2);
        #pragma unroll
        for (int nt = 0; nt < 8; nt++) {
            int col = bn + wn + nt * 8 + (lane & 3) * 2;
            float b0 = bias[col], b1 = bias[col + 1];
            #pragma unroll
            for (int h = 0; h < 2; h++) {
                int row = row0 + h * 8;
                if (row >= M) continue;
                float v0 = acc[mt][nt][h * 2 + 0] + b0;
                float v1 = acc[mt][nt][h * 2 + 1] + b1;
                if (MODE == 0) {
                    v0 *= alpha; v1 *= alpha;
                    *(uint32_t*)&((__half*)Cv)[(size_t)row * N + col] = packh2(v0, v1);
                } else if (MODE == 1) {
                    v0 = v0 / (1.0f + expf(-1.702f * v0));
                    v1 = v1 / (1.0f + expf(-1.702f * v1));
                    *(uint32_t*)&((__half*)Cv)[(size_t)row * N + col] = packh2(v0, v1);
                } else {
                    const float* rr = &res[(size_t)row * N + col];
                    v0 += rr[0]; v1 += rr[1];
                    *(float2*)&((float*)Cv)[(size_t)row * N + col] = make_float2(v0, v1);
                }
            }
        }
    }
}

template<int MODE>
__global__ __launch_bounds__(256, 2)
void gemm_h(const __half* __restrict__ A, const __half* __restrict__ B,
            const float* __restrict__ bias, const float* __restrict__ res,
            void* __restrict__ C, int M, int N, int K, float alpha)
{
    gemm_body<MODE>(A, B, bias, res, C, M, N, K, alpha,
                    blockIdx.y * GBM, blockIdx.x * GBN);
}

__global__ __launch_bounds__(256, 2)
void gemm_qkv(const __half* __restrict__ A,
              const __half* __restrict__ wq, const __half* __restrict__ wk,
              const __half* __restrict__ wv,
              const float* __restrict__ bq, const float* __restrict__ bk,
              const float* __restrict__ bv,
              __half* __restrict__ q, __half* __restrict__ k, __half* __restrict__ v,
              int M, int K)
{
    const int which = blockIdx.x >> 3;
    const int bn = (blockIdx.x & 7) * GBN;
    const __half* B   = (which == 0) ? wq : (which == 1) ? wk : wv;
    const float* bias = (which == 0) ? bq : (which == 1) ? bk : bv;
    __half* C         = (which == 0) ? q  : (which == 1) ? k  : v;
    const float alpha = (which == 0) ? QK_SCALE : 1.0f;
    gemm_body<0>(A, B, bias, nullptr, C, M, DMODEL, K, alpha,
                 blockIdx.y * GBM, bn);
}

// ---------------- fp16 tensor-core attention ----------------
#define AQT 64
#define AKT 64
#define NKT 5
#define QPH 72      // Q/KV tile pitch in halves (144B)
#define SPF 332     // fp32 score pitch
#define PPH 344     // half P pitch (688B)

#define OFF_QS   0
#define OFF_KVS  (AQT * QPH * 2)                       // 9216
#define OFF_SS   (OFF_KVS + AKT * QPH * 2)             // 18432
#define OFF_PS   (OFF_SS + AQT * SPF * 4)              // 103424
#define OFF_SINV (OFF_PS + AQT * PPH * 2)              // 147456
#define ATT_SMEM (OFF_SINV + AQT * 4)                  // 147712

__global__ __launch_bounds__(256)
void attn_h(const __half* __restrict__ Q, const __half* __restrict__ K,
            const __half* __restrict__ V, __half* __restrict__ O)
{
    extern __shared__ __align__(16) char smraw[];
    __half (*Qs)[QPH]  = (__half(*)[QPH])(smraw + OFF_QS);
    __half (*KVs)[QPH] = (__half(*)[QPH])(smraw + OFF_KVS);
    float  (*Ss)[SPF]  = (float(*)[SPF]) (smraw + OFF_SS);
    __half (*Ps)[PPH]  = (__half(*)[PPH])(smraw + OFF_PS);
    float* sinv        = (float*)(smraw + OFF_SINV);

    const int qt  = blockIdx.x * AQT;
    const int bh  = blockIdx.y;
    const int b   = bh >> 4, h = bh & 15;
    const size_t base = (size_t)b * NSEQ * DMODEL + (size_t)h * HDIM;
    const int tid  = threadIdx.x;
    const int lane = tid & 31;
    const int wid  = tid >> 5;
    const int wm   = (wid & 3) * 16;
    const int wn   = (wid >> 2) * 32;

    // load Q tile [64 q][64 d] (half, uint4 = 8 halves)
    #pragma unroll
    for (int i = 0; i < 2; i++) {
        int idx = tid + 256 * i;
        int row = idx >> 3, ch = idx & 7;
        uint4 v = make_uint4(0u, 0u, 0u, 0u);
        if (qt + row < NSEQ)
            v = *(const uint4*)&Q[base + (size_t)(qt + row) * DMODEL + ch * 8];
        *(uint4*)&Qs[row][ch * 8] = v;
    }

    // ---- phase 1: S = Q K^T ----
    for (int t = 0; t < NKT; t++) {
        int kt0 = t * AKT;
        __syncthreads();
        #pragma unroll
        for (int i = 0; i < 2; i++) {
            int idx = tid + 256 * i;
            int row = idx >> 3, ch = idx & 7;
            uint4 v = make_uint4(0u, 0u, 0u, 0u);
            if (kt0 + row < NSEQ)
                v = *(const uint4*)&K[base + (size_t)(kt0 + row) * DMODEL + ch * 8];
            *(uint4*)&KVs[row][ch * 8] = v;
        }
        __syncthreads();

        float accS[4][4];
        #pragma unroll
        for (int nt = 0; nt < 4; nt++)
            #pragma unroll
            for (int q = 0; q < 4; q++) accS[nt][q] = 0.f;

        #pragma unroll
        for (int ks = 0; ks < 4; ks++) {
            int kk = ks * 16 + (lane & 3) * 2;
            uint32_t af[4];
            int row = wm + (lane >> 2);
            af[0] = ld_u32(&Qs[row    ][kk    ]);
            af[1] = ld_u32(&Qs[row + 8][kk    ]);
            af[2] = ld_u32(&Qs[row    ][kk + 8]);
            af[3] = ld_u32(&Qs[row + 8][kk + 8]);
            #pragma unroll
            for (int nt = 0; nt < 4; nt++) {
                int col = wn + nt * 8 + (lane >> 2);
                uint32_t bf[2];
                bf[0] = ld_u32(&KVs[col][kk    ]);
                bf[1] = ld_u32(&KVs[col][kk + 8]);
                mma_f16(accS[nt], af, bf);
            }
        }
        int row = wm + (lane >> 2);
        #pragma unroll
        for (int nt = 0; nt < 4; nt++) {
            int col = kt0 + wn + nt * 8 + (lane & 3) * 2;
            Ss[row    ][col    ] = accS[nt][0];
            Ss[row    ][col + 1] = accS[nt][1];
            Ss[row + 8][col    ] = accS[nt][2];
            Ss[row + 8][col + 1] = accS[nt][3];
        }
    }
    __syncthreads();

    // ---- softmax (4 threads per row), P -> half ----
    {
        int row = tid >> 2, r = tid & 3;
        float m = -1e30f;
        for (int k = r; k < NSEQ; k += 4) m = fmaxf(m, Ss[row][k]);
        m = fmaxf(m, __shfl_xor_sync(0xffffffffu, m, 1));
        m = fmaxf(m, __shfl_xor_sync(0xffffffffu, m, 2));
        float sum = 0.f;
        for (int k = r; k < NKT * AKT; k += 4) {
            if (k < NSEQ) {
                float e = __expf(Ss[row][k] - m);
                Ps[row][k] = __float2half_rn(e);
                sum += e;
            } else {
                Ps[row][k] = __float2half_rn(0.f);
            }
        }
        sum += __shfl_xor_sync(0xffffffffu, sum, 1);
        sum += __shfl_xor_sync(0xffffffffu, sum, 2);
        if (r == 0) sinv[row] = 1.0f / sum;
    }

    // ---- phase 2: O = P V ----
    float accO[4][4];
    #pragma unroll
    for (int nt = 0; nt < 4; nt++)
        #pragma unroll
        for (int q = 0; q < 4; q++) accO[nt][q] = 0.f;

    for (int t = 0; t < NKT; t++) {
        int kt0 = t * AKT;
        __syncthreads();
        // V tile transposed: KVs[d][seq]
        #pragma unroll
        for (int i = 0; i < 2; i++) {
            int idx = tid + 256 * i;
            int row = idx >> 3, ch = idx & 7;
            uint4 v = make_uint4(0u, 0u, 0u, 0u);
            if (kt0 + row < NSEQ)
                v = *(const uint4*)&V[base + (size_t)(kt0 + row) * DMODEL + ch * 8];
            const __half* hv = (const __half*)&v;
            #pragma unroll
            for (int j = 0; j < 8; j++)
                KVs[ch * 8 + j][row] = hv[j];
        }
        __syncthreads();

        #pragma unroll
        for (int ks = 0; ks < 4; ks++) {
            int kk = ks * 16 + (lane & 3) * 2;
            uint32_t af[4];
            int row = wm + (lane >> 2);
            af[0] = ld_u32(&Ps[row    ][kt0 + kk    ]);
            af[1] = ld_u32(&Ps[row + 8][kt0 + kk    ]);
            af[2] = ld_u32(&Ps[row    ][kt0 + kk + 8]);
            af[3] = ld_u32(&Ps[row + 8][kt0 + kk + 8]);
            #pragma unroll
            for (int nt = 0; nt < 4; nt++) {
                int col = wn + nt * 8 + (lane >> 2);
                uint32_t bf[2];
                bf[0] = ld_u32(&KVs[col][kk    ]);
                bf[1] = ld_u32(&KVs[col][kk + 8]);
                mma_f16(accO[nt], af, bf);
            }
        }
    }

    // epilogue: scale, write half
    {
        int row = wm + (lane >> 2);
        float i0 = sinv[row], i1 = sinv[row + 8];
        #pragma unroll
        for (int nt = 0; nt < 4; nt++) {
            int col = wn + nt * 8 + (lane & 3) * 2;
            if (qt + row < NSEQ)
                *(uint32_t*)&O[base + (size_t)(qt + row) * DMODEL + col] =
                    packh2(accO[nt][0] * i0, accO[nt][1] * i0);
            if (qt + row + 8 < NSEQ)
                *(uint32_t*)&O[base + (size_t)(qt + row + 8) * DMODEL + col] =
                    packh2(accO[nt][2] * i1, accO[nt][3] * i1);
        }
    }
}

// ---------------- launch ----------------
extern "C" void kernel_launch(void* const* d_in, const int* in_sizes, int n_in,
                              void* d_out, int out_size)
{
    const float* hs     = (const float*)d_in[0];
    const float* ln1_w  = (const float*)d_in[1];
    const float* ln1_b  = (const float*)d_in[2];
    const float* wq     = (const float*)d_in[3];
    const float* bq     = (const float*)d_in[4];
    const float* wk     = (const float*)d_in[5];
    const float* bk     = (const float*)d_in[6];
    const float* wv     = (const float*)d_in[7];
    const float* bv     = (const float*)d_in[8];
    const float* wo     = (const float*)d_in[9];
    const float* bo     = (const float*)d_in[10];
    const float* ln2_w  = (const float*)d_in[11];
    const float* ln2_b  = (const float*)d_in[12];
    const float* fc1_w  = (const float*)d_in[13];
    const float* fc1_b  = (const float*)d_in[14];
    const float* fc2_w  = (const float*)d_in[15];
    const float* fc2_b  = (const float*)d_in[16];
    float* out          = (float*)d_out;

    static __half *xln=nullptr,*q=nullptr,*k=nullptr,*v=nullptr,*attn=nullptr,
                  *h2=nullptr,*ff=nullptr,
                  *wqh=nullptr,*wkh=nullptr,*wvh=nullptr,*woh=nullptr,
                  *fc1h=nullptr,*fc2h=nullptr;
    static float *hidden=nullptr;
    if (!xln) {
        cudaGetSymbolAddress((void**)&xln,    g_xln_h);
        cudaGetSymbolAddress((void**)&q,      g_q_h);
        cudaGetSymbolAddress((void**)&k,      g_k_h);
        cudaGetSymbolAddress((void**)&v,      g_v_h);
        cudaGetSymbolAddress((void**)&attn,   g_attn_h);
        cudaGetSymbolAddress((void**)&hidden, g_hidden);
        cudaGetSymbolAddress((void**)&h2,     g_h2_h);
        cudaGetSymbolAddress((void**)&ff,     g_ff_h);
        cudaGetSymbolAddress((void**)&wqh,    g_wq_h);
        cudaGetSymbolAddress((void**)&wkh,    g_wk_h);
        cudaGetSymbolAddress((void**)&wvh,    g_wv_h);
        cudaGetSymbolAddress((void**)&woh,    g_wo_h);
        cudaGetSymbolAddress((void**)&fc1h,   g_fc1_h);
        cudaGetSymbolAddress((void**)&fc2h,   g_fc2_h);
        cudaFuncSetAttribute(attn_h, cudaFuncAttributeMaxDynamicSharedMemorySize, ATT_SMEM);
    }

    const int mtiles = (TOK + GBM - 1) / GBM;   // 81
    const int n4w = DMODEL * DMODEL / 4;
    const int n4f = FFDIM * DMODEL / 4;

    // 0) convert weights to half
    cvt_half_kernel<<<n4w / 256, 256>>>((const float4*)wq,    (uint2*)wqh,  n4w);
    cvt_half_kernel<<<n4w / 256, 256>>>((const float4*)wk,    (uint2*)wkh,  n4w);
    cvt_half_kernel<<<n4w / 256, 256>>>((const float4*)wv,    (uint2*)wvh,  n4w);
    cvt_half_kernel<<<n4w / 256, 256>>>((const float4*)wo,    (uint2*)woh,  n4w);
    cvt_half_kernel<<<n4f / 256, 256>>>((const float4*)fc1_w, (uint2*)fc1h, n4f);
    cvt_half_kernel<<<n4f / 256, 256>>>((const float4*)fc2_w, (uint2*)fc2h, n4f);

    // 1) LN1 -> half
    ln_kernel<<<TOK, 256>>>(hs, ln1_w, ln1_b, xln);

    // 2) fused QKV projections (half out; Q pre-scaled)
    gemm_qkv<<<dim3(24, mtiles), 256>>>(xln, wqh, wkh, wvh, bq, bk, bv,
                                        q, k, v, TOK, DMODEL);

    // 3) attention (fp16 mma)
    attn_h<<<dim3((NSEQ + AQT - 1)/AQT, BATCH*NHEAD), 256, ATT_SMEM>>>(q, k, v, attn);

    // 4) O projection + residual -> fp32 hidden
    gemm_h<2><<<dim3(DMODEL/GBN, mtiles), 256>>>(attn, woh, bo, hs, hidden,
                                                 TOK, DMODEL, DMODEL, 1.0f);

    // 5) LN2 -> half
    ln_kernel<<<TOK, 256>>>(hidden, ln2_w, ln2_b, h2);

    // 6) FC1 + quick-gelu -> half
    gemm_h<1><<<dim3(FFDIM/GBN, mtiles), 256>>>(h2, fc1h, fc1_b, nullptr, ff,
                                                TOK, FFDIM, DMODEL, 1.0f);

    // 7) FC2 + residual -> fp32 output
    gemm_h<2><<<dim3(DMODEL/GBN, mtiles), 256>>>(ff, fc2h, fc2_b, hidden, out,
                                                 TOK, DMODEL, FFDIM, 1.0f);
}

// round 6
// speedup vs baseline: 11.6344x; 1.0297x over previous
#include <cuda_runtime.h>
#include <cuda_fp16.h>
#include <math.h>
#include <stdint.h>

// Problem constants
#define BATCH   40
#define NSEQ    257
#define DMODEL  1024
#define FFDIM   4096
#define NHEAD   16
#define HDIM    64
#define TOK     (BATCH * NSEQ)      // 10280
#define QK_SCALE 0.125f

// ---------------- scratch ----------------
__device__ __half g_xln_h [TOK * DMODEL];
__device__ __half g_q_h   [TOK * DMODEL];
__device__ __half g_k_h   [TOK * DMODEL];
__device__ __half g_v_h   [TOK * DMODEL];
__device__ __half g_attn_h[TOK * DMODEL];
__device__ float  g_hidden[TOK * DMODEL];
__device__ __half g_h2_h  [TOK * DMODEL];
__device__ __half g_ff_h  [TOK * FFDIM];
__device__ __half g_wq_h  [DMODEL * DMODEL];
__device__ __half g_wk_h  [DMODEL * DMODEL];
__device__ __half g_wv_h  [DMODEL * DMODEL];
__device__ __half g_wo_h  [DMODEL * DMODEL];
__device__ __half g_fc1_h [FFDIM * DMODEL];
__device__ __half g_fc2_h [DMODEL * FFDIM];

// ---------------- helpers ----------------
__device__ __forceinline__ float warpSum(float v) {
    #pragma unroll
    for (int o = 16; o > 0; o >>= 1) v += __shfl_xor_sync(0xffffffffu, v, o);
    return v;
}
__device__ __forceinline__ void mma_f16(float* d, const uint32_t* a, const uint32_t* b) {
    asm volatile(
        "mma.sync.aligned.m16n8k16.row.col.f32.f16.f16.f32 "
        "{%0,%1,%2,%3}, {%4,%5,%6,%7}, {%8,%9}, {%0,%1,%2,%3};"
        : "+f"(d[0]), "+f"(d[1]), "+f"(d[2]), "+f"(d[3])
        : "r"(a[0]), "r"(a[1]), "r"(a[2]), "r"(a[3]), "r"(b[0]), "r"(b[1]));
}
__device__ __forceinline__ uint32_t smem_u32(const void* p) {
    return (uint32_t)__cvta_generic_to_shared(p);
}
__device__ __forceinline__ void ldsm_x4(uint32_t& r0, uint32_t& r1, uint32_t& r2,
                                        uint32_t& r3, uint32_t addr) {
    asm volatile("ldmatrix.sync.aligned.m8n8.x4.shared.b16 {%0,%1,%2,%3}, [%4];"
                 : "=r"(r0), "=r"(r1), "=r"(r2), "=r"(r3) : "r"(addr));
}
__device__ __forceinline__ void ldsm_x4_t(uint32_t& r0, uint32_t& r1, uint32_t& r2,
                                          uint32_t& r3, uint32_t addr) {
    asm volatile("ldmatrix.sync.aligned.m8n8.x4.trans.shared.b16 {%0,%1,%2,%3}, [%4];"
                 : "=r"(r0), "=r"(r1), "=r"(r2), "=r"(r3) : "r"(addr));
}
__device__ __forceinline__ uint32_t packh2(float a, float b) {
    __half2 h = __floats2half2_rn(a, b);
    return *(uint32_t*)&h;
}

// ---------------- weight conversion: fp32 -> fp16 ----------------
__global__ void cvt_half_kernel(const float4* __restrict__ in, uint2* __restrict__ out, int n4)
{
    int i = blockIdx.x * blockDim.x + threadIdx.x;
    if (i < n4) {
        float4 v = in[i];
        uint2 o;
        o.x = packh2(v.x, v.y);
        o.y = packh2(v.z, v.w);
        out[i] = o;
    }
}

// ---------------- LayerNorm -> half out ----------------
__global__ void ln_kernel(const float* __restrict__ x,
                          const float* __restrict__ w,
                          const float* __restrict__ b,
                          __half* __restrict__ y)
{
    int row = blockIdx.x;
    int tid = threadIdx.x;
    const float* xr = x + (size_t)row * DMODEL;
    float4 v = *(const float4*)&xr[tid * 4];

    float s  = v.x + v.y + v.z + v.w;
    float s2 = v.x * v.x + v.y * v.y + v.z * v.z + v.w * v.w;

    __shared__ float redS[8], redS2[8];
    int lane = tid & 31, wid = tid >> 5;
    s  = warpSum(s);
    s2 = warpSum(s2);
    if (lane == 0) { redS[wid] = s; redS2[wid] = s2; }
    __syncthreads();
    float ts = 0.f, ts2 = 0.f;
    #pragma unroll
    for (int i = 0; i < 8; i++) { ts += redS[i]; ts2 += redS2[i]; }
    float mean = ts * (1.0f / DMODEL);
    float var  = ts2 * (1.0f / DMODEL) - mean * mean;
    float r    = rsqrtf(var + 1e-5f);

    float4 wv = *(const float4*)&w[tid * 4];
    float4 bv = *(const float4*)&b[tid * 4];
    float o0 = (v.x - mean) * r * wv.x + bv.x;
    float o1 = (v.y - mean) * r * wv.y + bv.y;
    float o2 = (v.z - mean) * r * wv.z + bv.z;
    float o3 = (v.w - mean) * r * wv.w + bv.w;
    uint2 st;
    st.x = packh2(o0, o1);
    st.y = packh2(o2, o3);
    *(uint2*)&y[(size_t)row * DMODEL + tid * 4] = st;
}

// ---------------- fp16 tensor-core NT GEMM (ldmatrix, 128x256) ----------------
// C[M,N] = epilogue(A[M,K] @ B[N,K]^T + bias)
// MODE 0: (acc+bias)*alpha -> half   MODE 1: quick-gelu -> half   MODE 2: +res -> float
#define GBM 128
#define GBN 256
#define GBK 32      // halves per K-tile
#define PH  40      // smem pitch in halves (80B)
#define STG 4

template<int MODE>
__device__ __forceinline__ void gemm_body(
    const __half* __restrict__ A, const __half* __restrict__ B,
    const float* __restrict__ bias, const float* __restrict__ res,
    void* __restrict__ Cv, int M, int N, int K, float alpha, int bm, int bn)
{
    __shared__ __half As[STG][GBM][PH];
    __shared__ __half Bs[STG][GBN][PH];

    const int tid  = threadIdx.x;
    const int lane = tid & 31;
    const int wid  = tid >> 5;
    const int wm   = (wid & 1) * 64;    // 2 warps over M (64 rows each)
    const int wn   = (wid >> 1) * 64;   // 4 warps over N (64 cols each)

    float acc[4][8][4];
    #pragma unroll
    for (int i = 0; i < 4; i++)
        #pragma unroll
        for (int j = 0; j < 8; j++)
            #pragma unroll
            for (int q = 0; q < 4; q++) acc[i][j][q] = 0.f;

    const int ktiles = K / GBK;

    auto load_tile = [&](int kt, int s) {
        // A: 128 rows x 4 chunks of 16B
        #pragma unroll
        for (int i = 0; i < 2; i++) {
            int idx = tid + 256 * i;
            int row = idx >> 2, ch = idx & 3;
            uint32_t dst = smem_u32(&As[s][row][ch * 8]);
            const __half* src = A + (size_t)(bm + row) * K + kt * GBK + ch * 8;
            int sz = (bm + row < M) ? 16 : 0;
            asm volatile("cp.async.ca.shared.global [%0], [%1], 16, %2;"
                         :: "r"(dst), "l"(src), "r"(sz));
        }
        // B: 256 rows x 4 chunks of 16B
        #pragma unroll
        for (int i = 0; i < 4; i++) {
            int idx = tid + 256 * i;
            int row = idx >> 2, ch = idx & 3;
            uint32_t dst = smem_u32(&Bs[s][row][ch * 8]);
            const __half* src = B + (size_t)(bn + row) * K + kt * GBK + ch * 8;
            asm volatile("cp.async.ca.shared.global [%0], [%1], 16;"
                         :: "r"(dst), "l"(src));
        }
        asm volatile("cp.async.commit_group;");
    };

    const int l15 = lane & 15;
    const int lhi = lane >> 4;           // 0/1 -> k-half selector for ldmatrix

    auto compute_tile = [&](int s) {
        #pragma unroll
        for (int ks = 0; ks < 2; ks++) {
            const int kc = ks * 16 + lhi * 8;    // ldmatrix col (halves)
            uint32_t af[4][4];
            uint32_t bf[8][2];
            #pragma unroll
            for (int mt = 0; mt < 4; mt++) {
                uint32_t adr = smem_u32(&As[s][wm + mt * 16 + l15][kc]);
                ldsm_x4(af[mt][0], af[mt][1], af[mt][2], af[mt][3], adr);
            }
            #pragma unroll
            for (int g = 0; g < 4; g++) {
                uint32_t adr = smem_u32(&Bs[s][wn + g * 16 + l15][kc]);
                ldsm_x4(bf[2*g][0], bf[2*g+1][0], bf[2*g][1], bf[2*g+1][1], adr);
            }
            #pragma unroll
            for (int mt = 0; mt < 4; mt++)
                #pragma unroll
                for (int nt = 0; nt < 8; nt++)
                    mma_f16(acc[mt][nt], af[mt], bf[nt]);
        }
    };

    #pragma unroll
    for (int s = 0; s < STG - 1; s++)
        if (s < ktiles) load_tile(s, s);

    int cur = 0, pre = STG - 1;
    for (int kt = 0; kt < ktiles; kt++) {
        asm volatile("cp.async.wait_group %0;" :: "n"(STG - 2));
        __syncthreads();
        if (kt + STG - 1 < ktiles) load_tile(kt + STG - 1, pre);
        compute_tile(cur);
        cur = (cur + 1 == STG) ? 0 : cur + 1;
        pre = (pre + 1 == STG) ? 0 : pre + 1;
    }

    // epilogue
    #pragma unroll
    for (int mt = 0; mt < 4; mt++) {
        int row0 = bm + wm + mt * 16 + (lane >> 2);
        #pragma unroll
        for (int nt = 0; nt < 8; nt++) {
            int col = bn + wn + nt * 8 + (lane & 3) * 2;
            float b0 = bias[col], b1 = bias[col + 1];
            #pragma unroll
            for (int h = 0; h < 2; h++) {
                int row = row0 + h * 8;
                if (row >= M) continue;
                float v0 = acc[mt][nt][h * 2 + 0] + b0;
                float v1 = acc[mt][nt][h * 2 + 1] + b1;
                if (MODE == 0) {
                    v0 *= alpha; v1 *= alpha;
                    *(uint32_t*)&((__half*)Cv)[(size_t)row * N + col] = packh2(v0, v1);
                } else if (MODE == 1) {
                    v0 = v0 / (1.0f + expf(-1.702f * v0));
                    v1 = v1 / (1.0f + expf(-1.702f * v1));
                    *(uint32_t*)&((__half*)Cv)[(size_t)row * N + col] = packh2(v0, v1);
                } else {
                    const float* rr = &res[(size_t)row * N + col];
                    v0 += rr[0]; v1 += rr[1];
                    *(float2*)&((float*)Cv)[(size_t)row * N + col] = make_float2(v0, v1);
                }
            }
        }
    }
}

template<int MODE>
__global__ __launch_bounds__(256, 1)
void gemm_h(const __half* __restrict__ A, const __half* __restrict__ B,
            const float* __restrict__ bias, const float* __restrict__ res,
            void* __restrict__ C, int M, int N, int K, float alpha)
{
    gemm_body<MODE>(A, B, bias, res, C, M, N, K, alpha,
                    blockIdx.y * GBM, blockIdx.x * GBN);
}

__global__ __launch_bounds__(256, 1)
void gemm_qkv(const __half* __restrict__ A,
              const __half* __restrict__ wq, const __half* __restrict__ wk,
              const __half* __restrict__ wv,
              const float* __restrict__ bq, const float* __restrict__ bk,
              const float* __restrict__ bv,
              __half* __restrict__ q, __half* __restrict__ k, __half* __restrict__ v,
              int M, int K)
{
    const int which = blockIdx.x >> 2;          // DMODEL/GBN = 4 tiles each
    const int bn = (blockIdx.x & 3) * GBN;
    const __half* B   = (which == 0) ? wq : (which == 1) ? wk : wv;
    const float* bias = (which == 0) ? bq : (which == 1) ? bk : bv;
    __half* C         = (which == 0) ? q  : (which == 1) ? k  : v;
    const float alpha = (which == 0) ? QK_SCALE : 1.0f;
    gemm_body<0>(A, B, bias, nullptr, C, M, DMODEL, K, alpha,
                 blockIdx.y * GBM, bn);
}

// ---------------- fp16 tensor-core attention (ldmatrix) ----------------
#define AQT 64
#define AKT 64
#define NKT 5
#define QPH 72      // Q/KV tile pitch in halves (144B)
#define SPF 332     // fp32 score pitch
#define PPH 344     // half P pitch (688B)

#define OFF_QS   0
#define OFF_KVS  (AQT * QPH * 2)
#define OFF_SS   (OFF_KVS + AKT * QPH * 2)
#define OFF_PS   (OFF_SS + AQT * SPF * 4)
#define OFF_SINV (OFF_PS + AQT * PPH * 2)
#define ATT_SMEM (OFF_SINV + AQT * 4)

__global__ __launch_bounds__(256)
void attn_h(const __half* __restrict__ Q, const __half* __restrict__ K,
            const __half* __restrict__ V, __half* __restrict__ O)
{
    extern __shared__ __align__(16) char smraw[];
    __half (*Qs)[QPH]  = (__half(*)[QPH])(smraw + OFF_QS);
    __half (*KVs)[QPH] = (__half(*)[QPH])(smraw + OFF_KVS);
    float  (*Ss)[SPF]  = (float(*)[SPF]) (smraw + OFF_SS);
    __half (*Ps)[PPH]  = (__half(*)[PPH])(smraw + OFF_PS);
    float* sinv        = (float*)(smraw + OFF_SINV);

    const int qt  = blockIdx.x * AQT;
    const int bh  = blockIdx.y;
    const int b   = bh >> 4, h = bh & 15;
    const size_t base = (size_t)b * NSEQ * DMODEL + (size_t)h * HDIM;
    const int tid  = threadIdx.x;
    const int lane = tid & 31;
    const int wid  = tid >> 5;
    const int wm   = (wid & 3) * 16;
    const int wn   = (wid >> 2) * 32;
    const int l15  = lane & 15;
    const int lhi  = lane >> 4;

    // load Q tile [64 q][64 d]
    #pragma unroll
    for (int i = 0; i < 2; i++) {
        int idx = tid + 256 * i;
        int row = idx >> 3, ch = idx & 7;
        uint4 v = make_uint4(0u, 0u, 0u, 0u);
        if (qt + row < NSEQ)
            v = *(const uint4*)&Q[base + (size_t)(qt + row) * DMODEL + ch * 8];
        *(uint4*)&Qs[row][ch * 8] = v;
    }

    // ---- phase 1: S = Q K^T ----
    for (int t = 0; t < NKT; t++) {
        int kt0 = t * AKT;
        __syncthreads();
        #pragma unroll
        for (int i = 0; i < 2; i++) {
            int idx = tid + 256 * i;
            int row = idx >> 3, ch = idx & 7;
            uint4 v = make_uint4(0u, 0u, 0u, 0u);
            if (kt0 + row < NSEQ)
                v = *(const uint4*)&K[base + (size_t)(kt0 + row) * DMODEL + ch * 8];
            *(uint4*)&KVs[row][ch * 8] = v;
        }
        __syncthreads();

        float accS[4][4];
        #pragma unroll
        for (int nt = 0; nt < 4; nt++)
            #pragma unroll
            for (int q = 0; q < 4; q++) accS[nt][q] = 0.f;

        #pragma unroll
        for (int ks = 0; ks < 4; ks++) {
            const int kc = ks * 16 + lhi * 8;
            uint32_t af[4];
            ldsm_x4(af[0], af[1], af[2], af[3],
                    smem_u32(&Qs[wm + l15][kc]));
            uint32_t bf[4][2];
            #pragma unroll
            for (int g = 0; g < 2; g++) {
                ldsm_x4(bf[2*g][0], bf[2*g+1][0], bf[2*g][1], bf[2*g+1][1],
                        smem_u32(&KVs[wn + g * 16 + l15][kc]));
            }
            #pragma unroll
            for (int nt = 0; nt < 4; nt++)
                mma_f16(accS[nt], af, bf[nt]);
        }
        int row = wm + (lane >> 2);
        #pragma unroll
        for (int nt = 0; nt < 4; nt++) {
            int col = kt0 + wn + nt * 8 + (lane & 3) * 2;
            Ss[row    ][col    ] = accS[nt][0];
            Ss[row    ][col + 1] = accS[nt][1];
            Ss[row + 8][col    ] = accS[nt][2];
            Ss[row + 8][col + 1] = accS[nt][3];
        }
    }
    __syncthreads();

    // ---- softmax (4 threads per row), P -> half ----
    {
        int row = tid >> 2, r = tid & 3;
        float m = -1e30f;
        for (int k = r; k < NSEQ; k += 4) m = fmaxf(m, Ss[row][k]);
        m = fmaxf(m, __shfl_xor_sync(0xffffffffu, m, 1));
        m = fmaxf(m, __shfl_xor_sync(0xffffffffu, m, 2));
        float sum = 0.f;
        for (int k = r; k < NKT * AKT; k += 4) {
            if (k < NSEQ) {
                float e = __expf(Ss[row][k] - m);
                Ps[row][k] = __float2half_rn(e);
                sum += e;
            } else {
                Ps[row][k] = __float2half_rn(0.f);
            }
        }
        sum += __shfl_xor_sync(0xffffffffu, sum, 1);
        sum += __shfl_xor_sync(0xffffffffu, sum, 2);
        if (r == 0) sinv[row] = 1.0f / sum;
    }

    // ---- phase 2: O = P V ----
    float accO[4][4];
    #pragma unroll
    for (int nt = 0; nt < 4; nt++)
        #pragma unroll
        for (int q = 0; q < 4; q++) accO[nt][q] = 0.f;

    for (int t = 0; t < NKT; t++) {
        int kt0 = t * AKT;
        __syncthreads();
        // V tile row-major [seq][d] (no transpose; ldmatrix.trans below)
        #pragma unroll
        for (int i = 0; i < 2; i++) {
            int idx = tid + 256 * i;
            int row = idx >> 3, ch = idx & 7;
            uint4 v = make_uint4(0u, 0u, 0u, 0u);
            if (kt0 + row < NSEQ)
                v = *(const uint4*)&V[base + (size_t)(kt0 + row) * DMODEL + ch * 8];
            *(uint4*)&KVs[row][ch * 8] = v;
        }
        __syncthreads();

        #pragma unroll
        for (int ks = 0; ks < 4; ks++) {
            const int kc = ks * 16 + lhi * 8;
            uint32_t af[4];
            ldsm_x4(af[0], af[1], af[2], af[3],
                    smem_u32(&Ps[wm + l15][kt0 + kc]));
            // V as col-major B via ldmatrix.trans: seq row = ks*16+(l&15), d col = wn+g*16+(l>>4)*8
            uint32_t bf[4][2];
            #pragma unroll
            for (int g = 0; g < 2; g++) {
                ldsm_x4_t(bf[2*g][0], bf[2*g][1], bf[2*g+1][0], bf[2*g+1][1],
                          smem_u32(&KVs[ks * 16 + l15][wn + g * 16 + lhi * 8]));
            }
            #pragma unroll
            for (int nt = 0; nt < 4; nt++)
                mma_f16(accO[nt], af, bf[nt]);
        }
    }

    // epilogue
    {
        int row = wm + (lane >> 2);
        float i0 = sinv[row], i1 = sinv[row + 8];
        #pragma unroll
        for (int nt = 0; nt < 4; nt++) {
            int col = wn + nt * 8 + (lane & 3) * 2;
            if (qt + row < NSEQ)
                *(uint32_t*)&O[base + (size_t)(qt + row) * DMODEL + col] =
                    packh2(accO[nt][0] * i0, accO[nt][1] * i0);
            if (qt + row + 8 < NSEQ)
                *(uint32_t*)&O[base + (size_t)(qt + row + 8) * DMODEL + col] =
                    packh2(accO[nt][2] * i1, accO[nt][3] * i1);
        }
    }
}

// ---------------- launch ----------------
extern "C" void kernel_launch(void* const* d_in, const int* in_sizes, int n_in,
                              void* d_out, int out_size)
{
    const float* hs     = (const float*)d_in[0];
    const float* ln1_w  = (const float*)d_in[1];
    const float* ln1_b  = (const float*)d_in[2];
    const float* wq     = (const float*)d_in[3];
    const float* bq     = (const float*)d_in[4];
    const float* wk     = (const float*)d_in[5];
    const float* bk     = (const float*)d_in[6];
    const float* wv     = (const float*)d_in[7];
    const float* bv     = (const float*)d_in[8];
    const float* wo     = (const float*)d_in[9];
    const float* bo     = (const float*)d_in[10];
    const float* ln2_w  = (const float*)d_in[11];
    const float* ln2_b  = (const float*)d_in[12];
    const float* fc1_w  = (const float*)d_in[13];
    const float* fc1_b  = (const float*)d_in[14];
    const float* fc2_w  = (const float*)d_in[15];
    const float* fc2_b  = (const float*)d_in[16];
    float* out          = (float*)d_out;

    static __half *xln=nullptr,*q=nullptr,*k=nullptr,*v=nullptr,*attn=nullptr,
                  *h2=nullptr,*ff=nullptr,
                  *wqh=nullptr,*wkh=nullptr,*wvh=nullptr,*woh=nullptr,
                  *fc1h=nullptr,*fc2h=nullptr;
    static float *hidden=nullptr;
    if (!xln) {
        cudaGetSymbolAddress((void**)&xln,    g_xln_h);
        cudaGetSymbolAddress((void**)&q,      g_q_h);
        cudaGetSymbolAddress((void**)&k,      g_k_h);
        cudaGetSymbolAddress((void**)&v,      g_v_h);
        cudaGetSymbolAddress((void**)&attn,   g_attn_h);
        cudaGetSymbolAddress((void**)&hidden, g_hidden);
        cudaGetSymbolAddress((void**)&h2,     g_h2_h);
        cudaGetSymbolAddress((void**)&ff,     g_ff_h);
        cudaGetSymbolAddress((void**)&wqh,    g_wq_h);
        cudaGetSymbolAddress((void**)&wkh,    g_wk_h);
        cudaGetSymbolAddress((void**)&wvh,    g_wv_h);
        cudaGetSymbolAddress((void**)&woh,    g_wo_h);
        cudaGetSymbolAddress((void**)&fc1h,   g_fc1_h);
        cudaGetSymbolAddress((void**)&fc2h,   g_fc2_h);
        cudaFuncSetAttribute(attn_h, cudaFuncAttributeMaxDynamicSharedMemorySize, ATT_SMEM);
    }

    const int mtiles = (TOK + GBM - 1) / GBM;   // 81
    const int n4w = DMODEL * DMODEL / 4;
    const int n4f = FFDIM * DMODEL / 4;

    // 0) convert weights to half
    cvt_half_kernel<<<n4w / 256, 256>>>((const float4*)wq,    (uint2*)wqh,  n4w);
    cvt_half_kernel<<<n4w / 256, 256>>>((const float4*)wk,    (uint2*)wkh,  n4w);
    cvt_half_kernel<<<n4w / 256, 256>>>((const float4*)wv,    (uint2*)wvh,  n4w);
    cvt_half_kernel<<<n4w / 256, 256>>>((const float4*)wo,    (uint2*)woh,  n4w);
    cvt_half_kernel<<<n4f / 256, 256>>>((const float4*)fc1_w, (uint2*)fc1h, n4f);
    cvt_half_kernel<<<n4f / 256, 256>>>((const float4*)fc2_w, (uint2*)fc2h, n4f);

    // 1) LN1 -> half
    ln_kernel<<<TOK, 256>>>(hs, ln1_w, ln1_b, xln);

    // 2) fused QKV projections
    gemm_qkv<<<dim3(12, mtiles), 256>>>(xln, wqh, wkh, wvh, bq, bk, bv,
                                        q, k, v, TOK, DMODEL);

    // 3) attention
    attn_h<<<dim3((NSEQ + AQT - 1)/AQT, BATCH*NHEAD), 256, ATT_SMEM>>>(q, k, v, attn);

    // 4) O projection + residual -> fp32 hidden
    gemm_h<2><<<dim3(DMODEL/GBN, mtiles), 256>>>(attn, woh, bo, hs, hidden,
                                                 TOK, DMODEL, DMODEL, 1.0f);

    // 5) LN2 -> half
    ln_kernel<<<TOK, 256>>>(hidden, ln2_w, ln2_b, h2);

    // 6) FC1 + quick-gelu -> half
    gemm_h<1><<<dim3(FFDIM/GBN, mtiles), 256>>>(h2, fc1h, fc1_b, nullptr, ff,
                                                TOK, FFDIM, DMODEL, 1.0f);

    // 7) FC2 + residual -> fp32 output
    gemm_h<2><<<dim3(DMODEL/GBN, mtiles), 256>>>(ff, fc2h, fc2_b, hidden, out,
                                                 TOK, DMODEL, FFDIM, 1.0f);
}